// round 3
// baseline (speedup 1.0000x reference)
#include <cuda_runtime.h>
#include <cuda_bf16.h>

typedef unsigned int uint;

#define BDIM 4
#define CDIM 512
#define HWD 4096
#define HIDD 256

// ---------------- scratch (device globals; allocation-free) ----------------
// packed-split format: uint = (bf16 hi) | (bf16 lo << 16), hi = rn(x), lo = rn(x-hi)
__device__ uint  g_cs_c[(size_t)BDIM * CDIM * HWD];   // content split
__device__ uint  g_cs_s[(size_t)BDIM * CDIM * HWD];   // style split
__device__ uint  g_mvn_c[(size_t)BDIM * CDIM * HWD];
__device__ uint  g_mvn_s[(size_t)BDIM * CDIM * HWD];
__device__ uint  g_Fq[(size_t)BDIM * CDIM * HWD];
__device__ uint  g_Gk[(size_t)BDIM * CDIM * HWD];
__device__ uint  g_Hv[(size_t)BDIM * CDIM * HWD];
__device__ uint  g_Obuf[(size_t)BDIM * CDIM * HWD];
__device__ float g_S[(size_t)BDIM * HWD * HWD];       // fp32 logits -> packed Sg in place
__device__ uint  g_A[(size_t)BDIM * HWD * HWD];       // affinity, packed
__device__ float g_hmid[(size_t)BDIM * HWD * HIDD];
__device__ float g_rn_c[(size_t)BDIM * HWD];
__device__ float g_rn_s[(size_t)BDIM * HWD];
__device__ float g_clamp[(size_t)BDIM * HWD];
__device__ uint  g_Wfs[CDIM * CDIM];
__device__ uint  g_Wgs[CDIM * CDIM];
__device__ uint  g_Whs[CDIM * CDIM];
__device__ uint  g_Wos[CDIM * CDIM];
__device__ uint  g_W1s[HIDD * HWD];

// ---------------- helpers ----------------
__device__ __forceinline__ uint packsplit(float x) {
    __nv_bfloat16 h = __float2bfloat16_rn(x);
    float hf = __bfloat162float(h);
    __nv_bfloat16 l = __float2bfloat16_rn(x - hf);
    return (uint)__bfloat16_as_ushort(h) | ((uint)__bfloat16_as_ushort(l) << 16);
}

__device__ __forceinline__ uint prmtb(uint a, uint b, uint s) {
    uint d;
    asm("prmt.b32 %0,%1,%2,%3;" : "=r"(d) : "r"(a), "r"(b), "r"(s));
    return d;
}

__device__ __forceinline__ void mma16(float* d, const uint* a, const uint* b) {
    asm volatile(
        "mma.sync.aligned.m16n8k16.row.col.f32.bf16.bf16.f32 "
        "{%0,%1,%2,%3},{%4,%5,%6,%7},{%8,%9},{%0,%1,%2,%3};"
        : "+f"(d[0]), "+f"(d[1]), "+f"(d[2]), "+f"(d[3])
        : "r"(a[0]), "r"(a[1]), "r"(a[2]), "r"(a[3]), "r"(b[0]), "r"(b[1]));
}

// ---------------- elementwise split converter ----------------
__global__ void split_kernel(const float4* __restrict__ x, uint4* __restrict__ y) {
    int i = blockIdx.x * 256 + threadIdx.x;
    float4 v = x[i];
    uint4 o;
    o.x = packsplit(v.x); o.y = packsplit(v.y);
    o.z = packsplit(v.z); o.w = packsplit(v.w);
    y[i] = o;
}

// ---------------- mvn: per (b,c) mean/var(ddof=1) -> packed split ----------------
__global__ void mvn_kernel(const float* __restrict__ x, uint* __restrict__ y) {
    int bc = blockIdx.x;
    const float* px = x + (size_t)bc * HWD;
    uint* py = y + (size_t)bc * HWD;
    int t = threadIdx.x;
    float s = 0.f, s2 = 0.f;
    for (int i = t; i < HWD; i += 256) { float v = px[i]; s += v; s2 += v * v; }
    __shared__ float r1[256], r2[256];
    r1[t] = s; r2[t] = s2; __syncthreads();
    for (int o = 128; o > 0; o >>= 1) {
        if (t < o) { r1[t] += r1[t + o]; r2[t] += r2[t + o]; }
        __syncthreads();
    }
    float mean = r1[0] * (1.0f / HWD);
    float var = (r2[0] - (float)HWD * mean * mean) * (1.0f / (HWD - 1));
    float inv = rsqrtf(var + 1e-5f);
    for (int i = t; i < HWD; i += 256) py[i] = packsplit((px[i] - mean) * inv);
}

// ---------------- reciprocal channel-L2 norm ----------------
__global__ void rnorm_kernel(const float* __restrict__ x, float* __restrict__ rn) {
    int b = blockIdx.y;
    int k = blockIdx.x * 256 + threadIdx.x;
    const float* px = x + (size_t)b * CDIM * HWD + k;
    float s = 0.f;
#pragma unroll 8
    for (int c = 0; c < CDIM; c++) { float v = px[(size_t)c * HWD]; s += v * v; }
    rn[b * HWD + k] = 1.0f / fmaxf(sqrtf(s), 1e-12f);
}

// ---------------- psi ----------------
__global__ void psi_kernel(const float* __restrict__ hmid, const float* __restrict__ W2,
                           const float* __restrict__ b2, float* __restrict__ clampv) {
    int row = blockIdx.x * 4 + (threadIdx.x >> 5);
    int lane = threadIdx.x & 31;
    const float* p = hmid + (size_t)row * HIDD;
    float s = 0.f;
#pragma unroll
    for (int j = lane; j < HIDD; j += 32) s += p[j] * W2[j];
#pragma unroll
    for (int o = 16; o > 0; o >>= 1) s += __shfl_xor_sync(0xffffffffu, s, o);
    if (lane == 0) {
        float psi = 1.f / (1.f + __expf(-(s + b2[0])));
        clampv[row] = psi * 0.5f + 0.4f;
    }
}

// ---------------- softmax + gate, fp32 in -> packed split out (in place) ----------------
__global__ void softgate_kernel(float* __restrict__ S, const float* __restrict__ clampv) {
    size_t row = blockIdx.x;
    float* p = S + row * HWD;
    __shared__ float buf[HWD];
    __shared__ float red[256];
    int t = threadIdx.x;
    float mx = -1e30f;
    for (int i = t; i < HWD; i += 256) { float v = p[i]; buf[i] = v; mx = fmaxf(mx, v); }
    red[t] = mx; __syncthreads();
    for (int o = 128; o > 0; o >>= 1) { if (t < o) red[t] = fmaxf(red[t], red[t + o]); __syncthreads(); }
    mx = red[0]; __syncthreads();
    float sum = 0.f;
    for (int i = t; i < HWD; i += 256) { float e = __expf(buf[i] - mx); buf[i] = e; sum += e; }
    red[t] = sum; __syncthreads();
    for (int o = 128; o > 0; o >>= 1) { if (t < o) red[t] += red[t + o]; __syncthreads(); }
    float inv = 1.0f / red[0];
    float cv = clampv[row];
    uint* po = (uint*)p;
    for (int i = t; i < HWD; i += 256) {
        float x = buf[i] * inv;
        po[i] = packsplit(1.0f / (1.0f + __expf(-50.0f * (x - cv))));
    }
}

// ---------------- bf16-split tensor-core GEMM, 128x128 tile, BK=16 ----------------
// operands are packed-split uint arrays.
// A logically MxK: A_KM -> stored [K,M]; B logically KxN: B_NK -> stored [N,K]
// smem: separate hi/lo bf16 planes, [c][k] with row stride 24 (conflict-free frags)

template <bool KM>
__device__ __forceinline__ void ldg_tile(const uint* __restrict__ P, int ld, int k0, int c0,
                                         uint4 (&r)[2], int t) {
#pragma unroll
    for (int i = 0; i < 2; i++) {
        int f = i * 256 + t;
        if (KM) {
            int kk = f >> 5, cc = (f & 31) << 2;
            r[i] = *(const uint4*)(P + (size_t)(k0 + kk) * ld + c0 + cc);
        } else {
            int cc = f >> 2, kk = (f & 3) << 2;
            r[i] = *(const uint4*)(P + (size_t)(c0 + cc) * ld + k0 + kk);
        }
    }
}

template <bool KM, bool SPLIT>
__device__ __forceinline__ void sts_tile(unsigned short* hi, unsigned short* lo,
                                         const uint4 (&r)[2], int t) {
#pragma unroll
    for (int i = 0; i < 2; i++) {
        int f = i * 256 + t;
        uint w0 = r[i].x, w1 = r[i].y, w2 = r[i].z, w3 = r[i].w;
        if (KM) {
            int kk = f >> 5, cc = (f & 31) << 2;
            hi[(cc + 0) * 24 + kk] = (unsigned short)w0;
            hi[(cc + 1) * 24 + kk] = (unsigned short)w1;
            hi[(cc + 2) * 24 + kk] = (unsigned short)w2;
            hi[(cc + 3) * 24 + kk] = (unsigned short)w3;
            if (SPLIT) {
                lo[(cc + 0) * 24 + kk] = (unsigned short)(w0 >> 16);
                lo[(cc + 1) * 24 + kk] = (unsigned short)(w1 >> 16);
                lo[(cc + 2) * 24 + kk] = (unsigned short)(w2 >> 16);
                lo[(cc + 3) * 24 + kk] = (unsigned short)(w3 >> 16);
            }
        } else {
            int cc = f >> 2, kk = (f & 3) << 2;
            *(uint*)(hi + cc * 24 + kk)     = prmtb(w0, w1, 0x5410);
            *(uint*)(hi + cc * 24 + kk + 2) = prmtb(w2, w3, 0x5410);
            if (SPLIT) {
                *(uint*)(lo + cc * 24 + kk)     = prmtb(w0, w1, 0x7632);
                *(uint*)(lo + cc * 24 + kk + 2) = prmtb(w2, w3, 0x7632);
            }
        }
    }
}

template <bool A_KM, bool B_NK, bool SPLIT>
__global__ __launch_bounds__(256)
void tc_gemm(const uint* __restrict__ A, const uint* __restrict__ B, float* __restrict__ C,
             int K, int lda, int ldb, int ldc,
             long long sA, long long sB, long long sC,
             const float* __restrict__ bias, int biasMode,
             const float* __restrict__ scaleM, long long sSM,
             const float* __restrict__ scaleN, long long sSN,
             const float* __restrict__ addSrc, long long sAdd,
             int actMode, int outMode) {
    __shared__ unsigned short AsH[2][128 * 24];
    __shared__ unsigned short AsL[2][128 * 24];
    __shared__ unsigned short BsH[2][128 * 24];
    __shared__ unsigned short BsL[2][128 * 24];
    int bz = blockIdx.z;
    A += sA * bz; B += sB * bz;
    float* Cb = C + sC * bz;
    int bm = blockIdx.y * 128, bn = blockIdx.x * 128;
    int t = threadIdx.x, w = t >> 5, lane = t & 31;
    int wm = (w >> 1) * 32, wn = (w & 1) * 64;
    int g = lane >> 2, tg = lane & 3;

    float acc[2][8][4];
#pragma unroll
    for (int mi = 0; mi < 2; mi++)
#pragma unroll
        for (int ni = 0; ni < 8; ni++)
#pragma unroll
            for (int r = 0; r < 4; r++) acc[mi][ni][r] = 0.f;

    uint4 rA[2], rB[2];
    ldg_tile<A_KM>(A, lda, 0, bm, rA, t);
    ldg_tile<!B_NK>(B, ldb, 0, bn, rB, t);
    sts_tile<A_KM, SPLIT>(AsH[0], AsL[0], rA, t);
    sts_tile<!B_NK, SPLIT>(BsH[0], BsL[0], rB, t);
    __syncthreads();

    int T = K / 16, p = 0;
    for (int kt = 0; kt < T; kt++) {
        if (kt + 1 < T) {
            ldg_tile<A_KM>(A, lda, (kt + 1) * 16, bm, rA, t);
            ldg_tile<!B_NK>(B, ldb, (kt + 1) * 16, bn, rB, t);
        }
        uint aH[2][4], aL[2][4], bH[8][2], bL[8][2];
#pragma unroll
        for (int mi = 0; mi < 2; mi++) {
            const unsigned short* pH = AsH[p] + (wm + mi * 16 + g) * 24 + 2 * tg;
            aH[mi][0] = *(const uint*)(pH);
            aH[mi][1] = *(const uint*)(pH + 8 * 24);
            aH[mi][2] = *(const uint*)(pH + 8);
            aH[mi][3] = *(const uint*)(pH + 8 * 24 + 8);
            if (SPLIT) {
                const unsigned short* pL = AsL[p] + (wm + mi * 16 + g) * 24 + 2 * tg;
                aL[mi][0] = *(const uint*)(pL);
                aL[mi][1] = *(const uint*)(pL + 8 * 24);
                aL[mi][2] = *(const uint*)(pL + 8);
                aL[mi][3] = *(const uint*)(pL + 8 * 24 + 8);
            }
        }
#pragma unroll
        for (int ni = 0; ni < 8; ni++) {
            const unsigned short* pH = BsH[p] + (wn + ni * 8 + g) * 24 + 2 * tg;
            bH[ni][0] = *(const uint*)(pH);
            bH[ni][1] = *(const uint*)(pH + 8);
            if (SPLIT) {
                const unsigned short* pL = BsL[p] + (wn + ni * 8 + g) * 24 + 2 * tg;
                bL[ni][0] = *(const uint*)(pL);
                bL[ni][1] = *(const uint*)(pL + 8);
            }
        }
#pragma unroll
        for (int mi = 0; mi < 2; mi++)
#pragma unroll
            for (int ni = 0; ni < 8; ni++) {
                mma16(acc[mi][ni], aH[mi], bH[ni]);
                if (SPLIT) {
                    mma16(acc[mi][ni], aH[mi], bL[ni]);
                    mma16(acc[mi][ni], aL[mi], bH[ni]);
                }
            }
        if (kt + 1 < T) {
            p ^= 1;
            sts_tile<A_KM, SPLIT>(AsH[p], AsL[p], rA, t);
            sts_tile<!B_NK, SPLIT>(BsH[p], BsL[p], rB, t);
            __syncthreads();
        }
    }

    // epilogue
#pragma unroll
    for (int mi = 0; mi < 2; mi++) {
#pragma unroll
        for (int ni = 0; ni < 8; ni++) {
#pragma unroll
            for (int half = 0; half < 2; half++) {
                int m = bm + wm + mi * 16 + g + half * 8;
                int n = bn + wn + ni * 8 + 2 * tg;
                float v0 = acc[mi][ni][half * 2 + 0];
                float v1 = acc[mi][ni][half * 2 + 1];
                if (scaleM) { float s = scaleM[sSM * bz + m]; v0 *= s; v1 *= s; }
                if (scaleN) { v0 *= scaleN[sSN * bz + n]; v1 *= scaleN[sSN * bz + n + 1]; }
                if (biasMode == 1) { float b = bias[m]; v0 += b; v1 += b; }
                if (biasMode == 2) { v0 += bias[n]; v1 += bias[n + 1]; }
                if (actMode == 1) {
                    v0 = (v0 > 0.f) ? v0 : 0.2f * v0;
                    v1 = (v1 > 0.f) ? v1 : 0.2f * v1;
                }
                if (addSrc) {
                    v0 += addSrc[sAdd * bz + (size_t)m * ldc + n];
                    v1 += addSrc[sAdd * bz + (size_t)m * ldc + n + 1];
                }
                if (outMode == 0) {
                    *(float2*)(Cb + (size_t)m * ldc + n) = make_float2(v0, v1);
                } else {
                    uint2 ov = make_uint2(packsplit(v0), packsplit(v1));
                    *(uint2*)((uint*)Cb + (size_t)m * ldc + n) = ov;
                }
            }
        }
    }
}

// ---------------- host launcher ----------------
extern "C" void kernel_launch(void* const* d_in, const int* in_sizes, int n_in,
                              void* d_out, int out_size) {
    const float* content = (const float*)d_in[0];
    const float* style   = (const float*)d_in[1];
    const float* Wf   = (const float*)d_in[2];
    const float* bf   = (const float*)d_in[3];
    const float* Wg   = (const float*)d_in[4];
    const float* bg   = (const float*)d_in[5];
    const float* Wh   = (const float*)d_in[6];
    const float* bh   = (const float*)d_in[7];
    const float* Wout = (const float*)d_in[8];
    const float* bout = (const float*)d_in[9];
    const float* W1   = (const float*)d_in[10];
    const float* b1   = (const float*)d_in[11];
    const float* W2   = (const float*)d_in[12];
    const float* b2   = (const float*)d_in[13];
    float* out = (float*)d_out;

    uint *csC, *csS, *mvnC, *mvnS, *Fq, *Gk, *Hv, *Obuf, *Amat;
    uint *Wfs, *Wgs, *Whs, *Wos, *W1s;
    float *S, *hmid, *rnC, *rnS, *clampv;
    cudaGetSymbolAddress((void**)&csC, g_cs_c);
    cudaGetSymbolAddress((void**)&csS, g_cs_s);
    cudaGetSymbolAddress((void**)&mvnC, g_mvn_c);
    cudaGetSymbolAddress((void**)&mvnS, g_mvn_s);
    cudaGetSymbolAddress((void**)&Fq, g_Fq);
    cudaGetSymbolAddress((void**)&Gk, g_Gk);
    cudaGetSymbolAddress((void**)&Hv, g_Hv);
    cudaGetSymbolAddress((void**)&Obuf, g_Obuf);
    cudaGetSymbolAddress((void**)&Amat, g_A);
    cudaGetSymbolAddress((void**)&S, g_S);
    cudaGetSymbolAddress((void**)&hmid, g_hmid);
    cudaGetSymbolAddress((void**)&rnC, g_rn_c);
    cudaGetSymbolAddress((void**)&rnS, g_rn_s);
    cudaGetSymbolAddress((void**)&clampv, g_clamp);
    cudaGetSymbolAddress((void**)&Wfs, g_Wfs);
    cudaGetSymbolAddress((void**)&Wgs, g_Wgs);
    cudaGetSymbolAddress((void**)&Whs, g_Whs);
    cudaGetSymbolAddress((void**)&Wos, g_Wos);
    cudaGetSymbolAddress((void**)&W1s, g_W1s);

    const long long CS = (long long)CDIM * HWD;
    const long long SS = (long long)HWD * HWD;
    const long long HS = (long long)HWD * HIDD;
    const int NBIG = BDIM * CDIM * HWD / 4 / 256;   // 8192 blocks
    const int NW   = CDIM * CDIM / 4 / 256;         // 256 blocks
    const int NW1  = HIDD * HWD / 4 / 256;          // 1024 blocks

    // 0) split conversions
    split_kernel<<<NBIG, 256>>>((const float4*)content, (uint4*)csC);
    split_kernel<<<NBIG, 256>>>((const float4*)style, (uint4*)csS);
    split_kernel<<<NW, 256>>>((const float4*)Wf, (uint4*)Wfs);
    split_kernel<<<NW, 256>>>((const float4*)Wg, (uint4*)Wgs);
    split_kernel<<<NW, 256>>>((const float4*)Wh, (uint4*)Whs);
    split_kernel<<<NW, 256>>>((const float4*)Wout, (uint4*)Wos);
    split_kernel<<<NW1, 256>>>((const float4*)W1, (uint4*)W1s);

    // 1) mvn -> packed split
    mvn_kernel<<<BDIM * CDIM, 256>>>(content, mvnC);
    mvn_kernel<<<BDIM * CDIM, 256>>>(style, mvnS);

    // 2) reciprocal L2 norms
    rnorm_kernel<<<dim3(HWD / 256, BDIM), 256>>>(content, rnC);
    rnorm_kernel<<<dim3(HWD / 256, BDIM), 256>>>(style, rnS);

    // 3) conv1x1 GEMMs (split) -> packed outputs
    dim3 gConv(HWD / 128, CDIM / 128, BDIM);
    tc_gemm<false, false, true><<<gConv, 256>>>(Wfs, mvnC, (float*)Fq, CDIM, CDIM, HWD, HWD,
        0, CS, CS, bf, 1, nullptr, 0, nullptr, 0, nullptr, 0, 0, 1);
    tc_gemm<false, false, true><<<gConv, 256>>>(Wgs, mvnS, (float*)Gk, CDIM, CDIM, HWD, HWD,
        0, CS, CS, bg, 1, nullptr, 0, nullptr, 0, nullptr, 0, 0, 1);
    tc_gemm<false, false, true><<<gConv, 256>>>(Whs, csS, (float*)Hv, CDIM, CDIM, HWD, HWD,
        0, CS, CS, bh, 1, nullptr, 0, nullptr, 0, nullptr, 0, 0, 1);

    // 4) attention logits (split) -> fp32 S
    dim3 gBig(HWD / 128, HWD / 128, BDIM);
    tc_gemm<true, false, true><<<gBig, 256>>>(Fq, Gk, S, CDIM, HWD, HWD, HWD,
        CS, CS, SS, nullptr, 0, nullptr, 0, nullptr, 0, nullptr, 0, 0, 0);

    // 5) affinity (plain bf16) -> packed A
    tc_gemm<true, false, false><<<gBig, 256>>>(csC, csS, (float*)Amat, CDIM, HWD, HWD, HWD,
        CS, CS, SS, nullptr, 0, rnC, HWD, rnS, HWD, nullptr, 0, 0, 1);

    // 6) hmid = leaky_relu(A @ W1^T + b1) (plain bf16) -> fp32
    dim3 gHmid(HIDD / 128, HWD / 128, BDIM);
    tc_gemm<false, true, false><<<gHmid, 256>>>(Amat, W1s, hmid, HWD, HWD, HWD, HIDD,
        SS, 0, HS, b1, 2, nullptr, 0, nullptr, 0, nullptr, 0, 1, 0);

    // 7) psi -> clamp
    psi_kernel<<<BDIM * HWD / 4, 128>>>(hmid, W2, b2, clampv);

    // 8) softmax + gate -> packed Sg in place
    softgate_kernel<<<BDIM * HWD, 256>>>(S, clampv);

    // 9) O = Hv @ Sg^T (split) -> packed Obuf
    dim3 gO(HWD / 128, CDIM / 128, BDIM);
    tc_gemm<false, true, true><<<gO, 256>>>(Hv, (uint*)S, (float*)Obuf, HWD, HWD, HWD, HWD,
        CS, SS, CS, nullptr, 0, nullptr, 0, nullptr, 0, nullptr, 0, 0, 1);

    // 10) out = Wout @ O + bout + content (split) -> fp32
    tc_gemm<false, false, true><<<gConv, 256>>>(Wos, Obuf, out, CDIM, CDIM, HWD, HWD,
        0, CS, CS, bout, 1, nullptr, 0, nullptr, 0, content, CS, 0, 0);
}

// round 7
// speedup vs baseline: 1.0035x; 1.0035x over previous
#include <cuda_runtime.h>
#include <cuda_bf16.h>

typedef unsigned int uint;

#define BDIM 4
#define CDIM 512
#define HWD 4096
#define HIDD 256

// ---------------- scratch (device globals; allocation-free) ----------------
// packed-split format: uint = (bf16 hi) | (bf16 lo << 16), hi = rn(x), lo = rn(x-hi)
__device__ uint  g_cs_c[(size_t)BDIM * CDIM * HWD];   // content split
__device__ uint  g_cs_s[(size_t)BDIM * CDIM * HWD];   // style split
__device__ uint  g_mvn_c[(size_t)BDIM * CDIM * HWD];
__device__ uint  g_mvn_s[(size_t)BDIM * CDIM * HWD];
__device__ uint  g_Fq[(size_t)BDIM * CDIM * HWD];
__device__ uint  g_Gk[(size_t)BDIM * CDIM * HWD];
__device__ uint  g_Hv[(size_t)BDIM * CDIM * HWD];
__device__ uint  g_Obuf[(size_t)BDIM * CDIM * HWD];
__device__ float g_S[(size_t)BDIM * HWD * HWD];       // fp32 logits -> packed Sg in place
__device__ uint  g_A[(size_t)BDIM * HWD * HWD];       // affinity, packed
__device__ float g_hmid[(size_t)BDIM * HWD * HIDD];
__device__ float g_rn_c[(size_t)BDIM * HWD];
__device__ float g_rn_s[(size_t)BDIM * HWD];
__device__ float g_clamp[(size_t)BDIM * HWD];
__device__ uint  g_Wfs[CDIM * CDIM];
__device__ uint  g_Wgs[CDIM * CDIM];
__device__ uint  g_Whs[CDIM * CDIM];
__device__ uint  g_Wos[CDIM * CDIM];
__device__ uint  g_W1s[HIDD * HWD];

// ---------------- helpers ----------------
__device__ __forceinline__ uint packsplit(float x) {
    __nv_bfloat16 h = __float2bfloat16_rn(x);
    float hf = __bfloat162float(h);
    __nv_bfloat16 l = __float2bfloat16_rn(x - hf);
    return (uint)__bfloat16_as_ushort(h) | ((uint)__bfloat16_as_ushort(l) << 16);
}

__device__ __forceinline__ uint prmtb(uint a, uint b, uint s) {
    uint d;
    asm("prmt.b32 %0,%1,%2,%3;" : "=r"(d) : "r"(a), "r"(b), "r"(s));
    return d;
}

__device__ __forceinline__ void mma16(float* d, const uint* a, const uint* b) {
    asm volatile(
        "mma.sync.aligned.m16n8k16.row.col.f32.bf16.bf16.f32 "
        "{%0,%1,%2,%3},{%4,%5,%6,%7},{%8,%9},{%0,%1,%2,%3};"
        : "+f"(d[0]), "+f"(d[1]), "+f"(d[2]), "+f"(d[3])
        : "r"(a[0]), "r"(a[1]), "r"(a[2]), "r"(a[3]), "r"(b[0]), "r"(b[1]));
}

// ---------------- elementwise split converter ----------------
__global__ void split_kernel(const float4* __restrict__ x, uint4* __restrict__ y) {
    int i = blockIdx.x * 256 + threadIdx.x;
    float4 v = x[i];
    uint4 o;
    o.x = packsplit(v.x); o.y = packsplit(v.y);
    o.z = packsplit(v.z); o.w = packsplit(v.w);
    y[i] = o;
}

// ---------------- mvn: per (b,c) mean/var(ddof=1) -> packed split ----------------
__global__ void mvn_kernel(const float* __restrict__ x, uint* __restrict__ y) {
    int bc = blockIdx.x;
    const float* px = x + (size_t)bc * HWD;
    uint* py = y + (size_t)bc * HWD;
    int t = threadIdx.x;
    float s = 0.f, s2 = 0.f;
    for (int i = t; i < HWD; i += 256) { float v = px[i]; s += v; s2 += v * v; }
    __shared__ float r1[256], r2[256];
    r1[t] = s; r2[t] = s2; __syncthreads();
    for (int o = 128; o > 0; o >>= 1) {
        if (t < o) { r1[t] += r1[t + o]; r2[t] += r2[t + o]; }
        __syncthreads();
    }
    float mean = r1[0] * (1.0f / HWD);
    float var = (r2[0] - (float)HWD * mean * mean) * (1.0f / (HWD - 1));
    float inv = rsqrtf(var + 1e-5f);
    for (int i = t; i < HWD; i += 256) py[i] = packsplit((px[i] - mean) * inv);
}

// ---------------- reciprocal channel-L2 norm ----------------
__global__ void rnorm_kernel(const float* __restrict__ x, float* __restrict__ rn) {
    int b = blockIdx.y;
    int k = blockIdx.x * 256 + threadIdx.x;
    const float* px = x + (size_t)b * CDIM * HWD + k;
    float s = 0.f;
#pragma unroll 8
    for (int c = 0; c < CDIM; c++) { float v = px[(size_t)c * HWD]; s += v * v; }
    rn[b * HWD + k] = 1.0f / fmaxf(sqrtf(s), 1e-12f);
}

// ---------------- psi ----------------
__global__ void psi_kernel(const float* __restrict__ hmid, const float* __restrict__ W2,
                           const float* __restrict__ b2, float* __restrict__ clampv) {
    int row = blockIdx.x * 4 + (threadIdx.x >> 5);
    int lane = threadIdx.x & 31;
    const float* p = hmid + (size_t)row * HIDD;
    float s = 0.f;
#pragma unroll
    for (int j = lane; j < HIDD; j += 32) s += p[j] * W2[j];
#pragma unroll
    for (int o = 16; o > 0; o >>= 1) s += __shfl_xor_sync(0xffffffffu, s, o);
    if (lane == 0) {
        float psi = 1.f / (1.f + __expf(-(s + b2[0])));
        clampv[row] = psi * 0.5f + 0.4f;
    }
}

// ---------------- softmax + gate, fp32 in -> packed split out (in place) ----------------
__global__ void softgate_kernel(float* __restrict__ S, const float* __restrict__ clampv) {
    size_t row = blockIdx.x;
    float* p = S + row * HWD;
    __shared__ float buf[HWD];
    __shared__ float red[256];
    int t = threadIdx.x;
    float mx = -1e30f;
    for (int i = t; i < HWD; i += 256) { float v = p[i]; buf[i] = v; mx = fmaxf(mx, v); }
    red[t] = mx; __syncthreads();
    for (int o = 128; o > 0; o >>= 1) { if (t < o) red[t] = fmaxf(red[t], red[t + o]); __syncthreads(); }
    mx = red[0]; __syncthreads();
    float sum = 0.f;
    for (int i = t; i < HWD; i += 256) { float e = __expf(buf[i] - mx); buf[i] = e; sum += e; }
    red[t] = sum; __syncthreads();
    for (int o = 128; o > 0; o >>= 1) { if (t < o) red[t] += red[t + o]; __syncthreads(); }
    float inv = 1.0f / red[0];
    float cv = clampv[row];
    uint* po = (uint*)p;
    for (int i = t; i < HWD; i += 256) {
        float x = buf[i] * inv;
        po[i] = packsplit(1.0f / (1.0f + __expf(-50.0f * (x - cv))));
    }
}

// ---------------- bf16-split tensor-core GEMM, 128x128 tile, BK=16 ----------------
// operands are packed-split uint arrays.
// A logically MxK: A_KM -> stored [K,M]; B logically KxN: B_NK -> stored [N,K]
// smem: separate hi/lo bf16 planes, [c][k] with row stride 24 (conflict-free frags)
// MMA schedule is PASS-MAJOR: 16 independent-accumulator MMAs per pass, so
// same-accumulator reuse distance is 16 issues (rt-bound, not latency-bound).

template <bool KM>
__device__ __forceinline__ void ldg_tile(const uint* __restrict__ P, int ld, int k0, int c0,
                                         uint4 (&r)[2], int t) {
#pragma unroll
    for (int i = 0; i < 2; i++) {
        int f = i * 256 + t;
        if (KM) {
            int kk = f >> 5, cc = (f & 31) << 2;
            r[i] = *(const uint4*)(P + (size_t)(k0 + kk) * ld + c0 + cc);
        } else {
            int cc = f >> 2, kk = (f & 3) << 2;
            r[i] = *(const uint4*)(P + (size_t)(c0 + cc) * ld + k0 + kk);
        }
    }
}

template <bool KM, bool SPLIT>
__device__ __forceinline__ void sts_tile(unsigned short* hi, unsigned short* lo,
                                         const uint4 (&r)[2], int t) {
#pragma unroll
    for (int i = 0; i < 2; i++) {
        int f = i * 256 + t;
        uint w0 = r[i].x, w1 = r[i].y, w2 = r[i].z, w3 = r[i].w;
        if (KM) {
            int kk = f >> 5, cc = (f & 31) << 2;
            hi[(cc + 0) * 24 + kk] = (unsigned short)w0;
            hi[(cc + 1) * 24 + kk] = (unsigned short)w1;
            hi[(cc + 2) * 24 + kk] = (unsigned short)w2;
            hi[(cc + 3) * 24 + kk] = (unsigned short)w3;
            if (SPLIT) {
                lo[(cc + 0) * 24 + kk] = (unsigned short)(w0 >> 16);
                lo[(cc + 1) * 24 + kk] = (unsigned short)(w1 >> 16);
                lo[(cc + 2) * 24 + kk] = (unsigned short)(w2 >> 16);
                lo[(cc + 3) * 24 + kk] = (unsigned short)(w3 >> 16);
            }
        } else {
            int cc = f >> 2, kk = (f & 3) << 2;
            *(uint*)(hi + cc * 24 + kk)     = prmtb(w0, w1, 0x5410);
            *(uint*)(hi + cc * 24 + kk + 2) = prmtb(w2, w3, 0x5410);
            if (SPLIT) {
                *(uint*)(lo + cc * 24 + kk)     = prmtb(w0, w1, 0x7632);
                *(uint*)(lo + cc * 24 + kk + 2) = prmtb(w2, w3, 0x7632);
            }
        }
    }
}

template <bool A_KM, bool B_NK, bool SPLIT>
__global__ __launch_bounds__(256)
void tc_gemm(const uint* __restrict__ A, const uint* __restrict__ B, float* __restrict__ C,
             int K, int lda, int ldb, int ldc,
             long long sA, long long sB, long long sC,
             const float* __restrict__ bias, int biasMode,
             const float* __restrict__ scaleM, long long sSM,
             const float* __restrict__ scaleN, long long sSN,
             const float* __restrict__ addSrc, long long sAdd,
             int actMode, int outMode) {
    __shared__ unsigned short AsH[2][128 * 24];
    __shared__ unsigned short AsL[2][128 * 24];
    __shared__ unsigned short BsH[2][128 * 24];
    __shared__ unsigned short BsL[2][128 * 24];
    int bz = blockIdx.z;
    A += sA * bz; B += sB * bz;
    float* Cb = C + sC * bz;
    int bm = blockIdx.y * 128, bn = blockIdx.x * 128;
    int t = threadIdx.x, w = t >> 5, lane = t & 31;
    int wm = (w >> 1) * 32, wn = (w & 1) * 64;
    int g = lane >> 2, tg = lane & 3;

    float acc[2][8][4];
#pragma unroll
    for (int mi = 0; mi < 2; mi++)
#pragma unroll
        for (int ni = 0; ni < 8; ni++)
#pragma unroll
            for (int r = 0; r < 4; r++) acc[mi][ni][r] = 0.f;

    uint4 rA[2], rB[2];
    ldg_tile<A_KM>(A, lda, 0, bm, rA, t);
    ldg_tile<!B_NK>(B, ldb, 0, bn, rB, t);
    sts_tile<A_KM, SPLIT>(AsH[0], AsL[0], rA, t);
    sts_tile<!B_NK, SPLIT>(BsH[0], BsL[0], rB, t);
    __syncthreads();

    int T = K / 16, p = 0;
    for (int kt = 0; kt < T; kt++) {
        if (kt + 1 < T) {
            ldg_tile<A_KM>(A, lda, (kt + 1) * 16, bm, rA, t);
            ldg_tile<!B_NK>(B, ldb, (kt + 1) * 16, bn, rB, t);
        }
        uint aH[2][4], aL[2][4], bH[8][2], bL[8][2];
#pragma unroll
        for (int mi = 0; mi < 2; mi++) {
            const unsigned short* pH = AsH[p] + (wm + mi * 16 + g) * 24 + 2 * tg;
            aH[mi][0] = *(const uint*)(pH);
            aH[mi][1] = *(const uint*)(pH + 8 * 24);
            aH[mi][2] = *(const uint*)(pH + 8);
            aH[mi][3] = *(const uint*)(pH + 8 * 24 + 8);
            if (SPLIT) {
                const unsigned short* pL = AsL[p] + (wm + mi * 16 + g) * 24 + 2 * tg;
                aL[mi][0] = *(const uint*)(pL);
                aL[mi][1] = *(const uint*)(pL + 8 * 24);
                aL[mi][2] = *(const uint*)(pL + 8);
                aL[mi][3] = *(const uint*)(pL + 8 * 24 + 8);
            }
        }
#pragma unroll
        for (int ni = 0; ni < 8; ni++) {
            const unsigned short* pH = BsH[p] + (wn + ni * 8 + g) * 24 + 2 * tg;
            bH[ni][0] = *(const uint*)(pH);
            bH[ni][1] = *(const uint*)(pH + 8);
            if (SPLIT) {
                const unsigned short* pL = BsL[p] + (wn + ni * 8 + g) * 24 + 2 * tg;
                bL[ni][0] = *(const uint*)(pL);
                bL[ni][1] = *(const uint*)(pL + 8);
            }
        }
        // PASS-MAJOR schedule: each pass touches all 16 accumulators once.
#pragma unroll
        for (int mi = 0; mi < 2; mi++)
#pragma unroll
            for (int ni = 0; ni < 8; ni++)
                mma16(acc[mi][ni], aH[mi], bH[ni]);
        if (SPLIT) {
#pragma unroll
            for (int mi = 0; mi < 2; mi++)
#pragma unroll
                for (int ni = 0; ni < 8; ni++)
                    mma16(acc[mi][ni], aH[mi], bL[ni]);
#pragma unroll
            for (int mi = 0; mi < 2; mi++)
#pragma unroll
                for (int ni = 0; ni < 8; ni++)
                    mma16(acc[mi][ni], aL[mi], bH[ni]);
        }
        if (kt + 1 < T) {
            p ^= 1;
            sts_tile<A_KM, SPLIT>(AsH[p], AsL[p], rA, t);
            sts_tile<!B_NK, SPLIT>(BsH[p], BsL[p], rB, t);
            __syncthreads();
        }
    }

    // epilogue
#pragma unroll
    for (int mi = 0; mi < 2; mi++) {
#pragma unroll
        for (int ni = 0; ni < 8; ni++) {
#pragma unroll
            for (int half = 0; half < 2; half++) {
                int m = bm + wm + mi * 16 + g + half * 8;
                int n = bn + wn + ni * 8 + 2 * tg;
                float v0 = acc[mi][ni][half * 2 + 0];
                float v1 = acc[mi][ni][half * 2 + 1];
                if (scaleM) { float s = scaleM[sSM * bz + m]; v0 *= s; v1 *= s; }
                if (scaleN) { v0 *= scaleN[sSN * bz + n]; v1 *= scaleN[sSN * bz + n + 1]; }
                if (biasMode == 1) { float b = bias[m]; v0 += b; v1 += b; }
                if (biasMode == 2) { v0 += bias[n]; v1 += bias[n + 1]; }
                if (actMode == 1) {
                    v0 = (v0 > 0.f) ? v0 : 0.2f * v0;
                    v1 = (v1 > 0.f) ? v1 : 0.2f * v1;
                }
                if (addSrc) {
                    v0 += addSrc[sAdd * bz + (size_t)m * ldc + n];
                    v1 += addSrc[sAdd * bz + (size_t)m * ldc + n + 1];
                }
                if (outMode == 0) {
                    *(float2*)(Cb + (size_t)m * ldc + n) = make_float2(v0, v1);
                } else {
                    uint2 ov = make_uint2(packsplit(v0), packsplit(v1));
                    *(uint2*)((uint*)Cb + (size_t)m * ldc + n) = ov;
                }
            }
        }
    }
}

// ---------------- host launcher ----------------
extern "C" void kernel_launch(void* const* d_in, const int* in_sizes, int n_in,
                              void* d_out, int out_size) {
    const float* content = (const float*)d_in[0];
    const float* style   = (const float*)d_in[1];
    const float* Wf   = (const float*)d_in[2];
    const float* bf   = (const float*)d_in[3];
    const float* Wg   = (const float*)d_in[4];
    const float* bg   = (const float*)d_in[5];
    const float* Wh   = (const float*)d_in[6];
    const float* bh   = (const float*)d_in[7];
    const float* Wout = (const float*)d_in[8];
    const float* bout = (const float*)d_in[9];
    const float* W1   = (const float*)d_in[10];
    const float* b1   = (const float*)d_in[11];
    const float* W2   = (const float*)d_in[12];
    const float* b2   = (const float*)d_in[13];
    float* out = (float*)d_out;

    uint *csC, *csS, *mvnC, *mvnS, *Fq, *Gk, *Hv, *Obuf, *Amat;
    uint *Wfs, *Wgs, *Whs, *Wos, *W1s;
    float *S, *hmid, *rnC, *rnS, *clampv;
    cudaGetSymbolAddress((void**)&csC, g_cs_c);
    cudaGetSymbolAddress((void**)&csS, g_cs_s);
    cudaGetSymbolAddress((void**)&mvnC, g_mvn_c);
    cudaGetSymbolAddress((void**)&mvnS, g_mvn_s);
    cudaGetSymbolAddress((void**)&Fq, g_Fq);
    cudaGetSymbolAddress((void**)&Gk, g_Gk);
    cudaGetSymbolAddress((void**)&Hv, g_Hv);
    cudaGetSymbolAddress((void**)&Obuf, g_Obuf);
    cudaGetSymbolAddress((void**)&Amat, g_A);
    cudaGetSymbolAddress((void**)&S, g_S);
    cudaGetSymbolAddress((void**)&hmid, g_hmid);
    cudaGetSymbolAddress((void**)&rnC, g_rn_c);
    cudaGetSymbolAddress((void**)&rnS, g_rn_s);
    cudaGetSymbolAddress((void**)&clampv, g_clamp);
    cudaGetSymbolAddress((void**)&Wfs, g_Wfs);
    cudaGetSymbolAddress((void**)&Wgs, g_Wgs);
    cudaGetSymbolAddress((void**)&Whs, g_Whs);
    cudaGetSymbolAddress((void**)&Wos, g_Wos);
    cudaGetSymbolAddress((void**)&W1s, g_W1s);

    const long long CS = (long long)CDIM * HWD;
    const long long SS = (long long)HWD * HWD;
    const long long HS = (long long)HWD * HIDD;
    const int NBIG = BDIM * CDIM * HWD / 4 / 256;
    const int NW   = CDIM * CDIM / 4 / 256;
    const int NW1  = HIDD * HWD / 4 / 256;

    // 0) split conversions
    split_kernel<<<NBIG, 256>>>((const float4*)content, (uint4*)csC);
    split_kernel<<<NBIG, 256>>>((const float4*)style, (uint4*)csS);
    split_kernel<<<NW, 256>>>((const float4*)Wf, (uint4*)Wfs);
    split_kernel<<<NW, 256>>>((const float4*)Wg, (uint4*)Wgs);
    split_kernel<<<NW, 256>>>((const float4*)Wh, (uint4*)Whs);
    split_kernel<<<NW, 256>>>((const float4*)Wout, (uint4*)Wos);
    split_kernel<<<NW1, 256>>>((const float4*)W1, (uint4*)W1s);

    // 1) mvn -> packed split
    mvn_kernel<<<BDIM * CDIM, 256>>>(content, mvnC);
    mvn_kernel<<<BDIM * CDIM, 256>>>(style, mvnS);

    // 2) reciprocal L2 norms
    rnorm_kernel<<<dim3(HWD / 256, BDIM), 256>>>(content, rnC);
    rnorm_kernel<<<dim3(HWD / 256, BDIM), 256>>>(style, rnS);

    // 3) conv1x1 GEMMs (split) -> packed outputs
    dim3 gConv(HWD / 128, CDIM / 128, BDIM);
    tc_gemm<false, false, true><<<gConv, 256>>>(Wfs, mvnC, (float*)Fq, CDIM, CDIM, HWD, HWD,
        0, CS, CS, bf, 1, nullptr, 0, nullptr, 0, nullptr, 0, 0, 1);
    tc_gemm<false, false, true><<<gConv, 256>>>(Wgs, mvnS, (float*)Gk, CDIM, CDIM, HWD, HWD,
        0, CS, CS, bg, 1, nullptr, 0, nullptr, 0, nullptr, 0, 0, 1);
    tc_gemm<false, false, true><<<gConv, 256>>>(Whs, csS, (float*)Hv, CDIM, CDIM, HWD, HWD,
        0, CS, CS, bh, 1, nullptr, 0, nullptr, 0, nullptr, 0, 0, 1);

    // 4) attention logits (split) -> fp32 S
    dim3 gBig(HWD / 128, HWD / 128, BDIM);
    tc_gemm<true, false, true><<<gBig, 256>>>(Fq, Gk, S, CDIM, HWD, HWD, HWD,
        CS, CS, SS, nullptr, 0, nullptr, 0, nullptr, 0, nullptr, 0, 0, 0);

    // 5) affinity (plain bf16) -> packed A
    tc_gemm<true, false, false><<<gBig, 256>>>(csC, csS, (float*)Amat, CDIM, HWD, HWD, HWD,
        CS, CS, SS, nullptr, 0, rnC, HWD, rnS, HWD, nullptr, 0, 0, 1);

    // 6) hmid = leaky_relu(A @ W1^T + b1) (plain bf16) -> fp32
    dim3 gHmid(HIDD / 128, HWD / 128, BDIM);
    tc_gemm<false, true, false><<<gHmid, 256>>>(Amat, W1s, hmid, HWD, HWD, HWD, HIDD,
        SS, 0, HS, b1, 2, nullptr, 0, nullptr, 0, nullptr, 0, 1, 0);

    // 7) psi -> clamp
    psi_kernel<<<BDIM * HWD / 4, 128>>>(hmid, W2, b2, clampv);

    // 8) softmax + gate -> packed Sg in place
    softgate_kernel<<<BDIM * HWD, 256>>>(S, clampv);

    // 9) O = Hv @ Sg^T (split) -> packed Obuf
    dim3 gO(HWD / 128, CDIM / 128, BDIM);
    tc_gemm<false, true, true><<<gO, 256>>>(Hv, (uint*)S, (float*)Obuf, HWD, HWD, HWD, HWD,
        CS, SS, CS, nullptr, 0, nullptr, 0, nullptr, 0, nullptr, 0, 0, 1);

    // 10) out = Wout @ O + bout + content (split) -> fp32
    tc_gemm<false, false, true><<<gConv, 256>>>(Wos, Obuf, out, CDIM, CDIM, HWD, HWD,
        0, CS, CS, bout, 1, nullptr, 0, nullptr, 0, content, CS, 0, 0);
}

// round 8
// speedup vs baseline: 1.3956x; 1.3908x over previous
#include <cuda_runtime.h>
#include <cuda_bf16.h>
#include <cuda_fp16.h>

typedef unsigned int uint;

#define BDIM 4
#define CDIM 512
#define HWD 4096
#define HIDD 256

// ---------------- scratch ----------------
// packed-split: uint = (bf16 hi) | (bf16 lo << 16)
__device__ uint   g_mvn_c[(size_t)BDIM * CDIM * HWD];
__device__ uint   g_mvn_s[(size_t)BDIM * CDIM * HWD];
__device__ uint   g_Fq[(size_t)BDIM * CDIM * HWD];     // [C,HW] packed
__device__ uint   g_Gk[(size_t)BDIM * CDIM * HWD];
__device__ float  g_S[(size_t)BDIM * HWD * HWD];       // fp32 logits -> fp16 Sg in place
__device__ __half g_styleT[(size_t)BDIM * HWD * CDIM]; // style^T fp16 [HW,C]
__device__ __half g_contentT[(size_t)BDIM * HWD * CDIM];
__device__ __half g_styleR[(size_t)BDIM * CDIM * HWD]; // style * rnS fp16 [C,HW]
__device__ __half g_Hv[(size_t)BDIM * CDIM * HWD];     // [C,HW] fp16
__device__ __half g_Ot[(size_t)BDIM * HWD * CDIM];     // [HW,C] fp16
__device__ __half g_T1t[(size_t)BDIM * HIDD * CDIM];   // [HID,C] fp16
__device__ float  g_hmid[(size_t)BDIM * HWD * HIDD];
__device__ float  g_rnC[BDIM * HWD];
__device__ float  g_rnS[BDIM * HWD];
__device__ float  g_clamp[BDIM * HWD];
__device__ uint   g_Wfs[CDIM * CDIM];
__device__ uint   g_Wgs[CDIM * CDIM];
__device__ __half g_Whs[CDIM * CDIM];
__device__ __half g_Wos[CDIM * CDIM];
__device__ __half g_W1h[HIDD * HWD];

// ---------------- helpers ----------------
__device__ __forceinline__ uint packsplit(float x) {
    __nv_bfloat16 h = __float2bfloat16_rn(x);
    float hf = __bfloat162float(h);
    __nv_bfloat16 l = __float2bfloat16_rn(x - hf);
    return (uint)__bfloat16_as_ushort(h) | ((uint)__bfloat16_as_ushort(l) << 16);
}
__device__ __forceinline__ uint prmtb(uint a, uint b, uint s) {
    uint d;
    asm("prmt.b32 %0,%1,%2,%3;" : "=r"(d) : "r"(a), "r"(b), "r"(s));
    return d;
}
__device__ __forceinline__ void mma_bf(float* d, const uint* a, const uint* b) {
    asm volatile(
        "mma.sync.aligned.m16n8k16.row.col.f32.bf16.bf16.f32 "
        "{%0,%1,%2,%3},{%4,%5,%6,%7},{%8,%9},{%0,%1,%2,%3};"
        : "+f"(d[0]), "+f"(d[1]), "+f"(d[2]), "+f"(d[3])
        : "r"(a[0]), "r"(a[1]), "r"(a[2]), "r"(a[3]), "r"(b[0]), "r"(b[1]));
}
__device__ __forceinline__ void mma_hf(float* d, const uint* a, const uint* b) {
    asm volatile(
        "mma.sync.aligned.m16n8k16.row.col.f32.f16.f16.f32 "
        "{%0,%1,%2,%3},{%4,%5,%6,%7},{%8,%9},{%0,%1,%2,%3};"
        : "+f"(d[0]), "+f"(d[1]), "+f"(d[2]), "+f"(d[3])
        : "r"(a[0]), "r"(a[1]), "r"(a[2]), "r"(a[3]), "r"(b[0]), "r"(b[1]));
}

// ---------------- elementwise kernels ----------------
__global__ void split_kernel(const float4* __restrict__ x, uint4* __restrict__ y) {
    int i = blockIdx.x * 256 + threadIdx.x;
    float4 v = x[i];
    y[i] = make_uint4(packsplit(v.x), packsplit(v.y), packsplit(v.z), packsplit(v.w));
}

__global__ void tohalf_kernel(const float4* __restrict__ x, __half* __restrict__ y) {
    int i = blockIdx.x * 256 + threadIdx.x;
    float4 v = x[i];
    __half2* o = (__half2*)(y + (size_t)i * 4);
    o[0] = __floats2half2_rn(v.x, v.y);
    o[1] = __floats2half2_rn(v.z, v.w);
}

// styleR[b,c,l] = fp16(style[b,c,l] * rnS[b,l])
__global__ void scalehalf_kernel(const float* __restrict__ x, const float* __restrict__ rn,
                                 __half* __restrict__ y) {
    int b = blockIdx.y;
    size_t i = (size_t)blockIdx.x * 256 + threadIdx.x;     // over C*HW/4
    size_t base = (size_t)b * CDIM * HWD + i * 4;
    int l = (int)((i * 4) % HWD);
    float4 v = *(const float4*)(x + base);
    float4 r = *(const float4*)(rn + (size_t)b * HWD + l);
    __half2* o = (__half2*)(y + base);
    o[0] = __floats2half2_rn(v.x * r.x, v.y * r.y);
    o[1] = __floats2half2_rn(v.z * r.z, v.w * r.w);
}

__global__ void mvn_kernel(const float* __restrict__ x, uint* __restrict__ y) {
    int bc = blockIdx.x;
    const float* px = x + (size_t)bc * HWD;
    uint* py = y + (size_t)bc * HWD;
    int t = threadIdx.x;
    float s = 0.f, s2 = 0.f;
    for (int i = t; i < HWD; i += 256) { float v = px[i]; s += v; s2 += v * v; }
    __shared__ float r1[256], r2[256];
    r1[t] = s; r2[t] = s2; __syncthreads();
    for (int o = 128; o > 0; o >>= 1) {
        if (t < o) { r1[t] += r1[t + o]; r2[t] += r2[t + o]; }
        __syncthreads();
    }
    float mean = r1[0] * (1.0f / HWD);
    float var = (r2[0] - (float)HWD * mean * mean) * (1.0f / (HWD - 1));
    float inv = rsqrtf(var + 1e-5f);
    for (int i = t; i < HWD; i += 256) py[i] = packsplit((px[i] - mean) * inv);
}

__global__ void rnorm_kernel(const float* __restrict__ x, float* __restrict__ rn) {
    int b = blockIdx.y;
    int k = blockIdx.x * 256 + threadIdx.x;
    const float* px = x + (size_t)b * CDIM * HWD + k;
    float s = 0.f;
#pragma unroll 8
    for (int c = 0; c < CDIM; c++) { float v = px[(size_t)c * HWD]; s += v * v; }
    rn[b * HWD + k] = 1.0f / fmaxf(sqrtf(s), 1e-12f);
}

// transpose [B][C][HW] fp32 -> [B][HW][C] fp16
__global__ void thalf_kernel(const float* __restrict__ x, __half* __restrict__ y) {
    __shared__ float tile[32][33];
    int b = blockIdx.z;
    int c0 = blockIdx.y * 32, h0 = blockIdx.x * 32;
    int tx = threadIdx.x, ty = threadIdx.y;
#pragma unroll
    for (int j = 0; j < 4; j++) {
        int c = c0 + ty + j * 8;
        tile[ty + j * 8][tx] = x[((size_t)b * CDIM + c) * HWD + h0 + tx];
    }
    __syncthreads();
#pragma unroll
    for (int j = 0; j < 4; j++) {
        int h = h0 + ty + j * 8;
        y[((size_t)b * HWD + h) * CDIM + c0 + tx] = __float2half_rn(tile[tx][ty + j * 8]);
    }
}

__global__ void psi_kernel(const float* __restrict__ hmid, const float* __restrict__ W2,
                           const float* __restrict__ b2, float* __restrict__ clampv) {
    int row = blockIdx.x * 4 + (threadIdx.x >> 5);
    int lane = threadIdx.x & 31;
    const float* p = hmid + (size_t)row * HIDD;
    float s = 0.f;
#pragma unroll
    for (int j = lane; j < HIDD; j += 32) s += p[j] * W2[j];
#pragma unroll
    for (int o = 16; o > 0; o >>= 1) s += __shfl_xor_sync(0xffffffffu, s, o);
    if (lane == 0) {
        float psi = 1.f / (1.f + __expf(-(s + b2[0])));
        clampv[row] = psi * 0.5f + 0.4f;
    }
}

// softmax + gate: fp32 logits -> fp16 Sg, in place
__global__ void softgate_kernel(float* __restrict__ S, const float* __restrict__ clampv) {
    size_t row = blockIdx.x;
    float* p = S + row * HWD;
    __shared__ float buf[HWD];
    __shared__ float red[256];
    int t = threadIdx.x;
    float mx = -1e30f;
    for (int i = t; i < HWD; i += 256) { float v = p[i]; buf[i] = v; mx = fmaxf(mx, v); }
    red[t] = mx; __syncthreads();
    for (int o = 128; o > 0; o >>= 1) { if (t < o) red[t] = fmaxf(red[t], red[t + o]); __syncthreads(); }
    mx = red[0]; __syncthreads();
    float sum = 0.f;
    for (int i = t; i < HWD; i += 256) { float e = __expf(buf[i] - mx); buf[i] = e; sum += e; }
    red[t] = sum; __syncthreads();
    for (int o = 128; o > 0; o >>= 1) { if (t < o) red[t] += red[t + o]; __syncthreads(); }
    float inv = 1.0f / red[0];
    float cv = clampv[row];
    __half* po = (__half*)p;
    for (int i = t; i < HWD; i += 256) {
        float x = buf[i] * inv;
        po[i] = __float2half_rn(1.0f / (1.0f + __expf(-50.0f * (x - cv))));
    }
}

// ---------------- bf16-split GEMM (128x128, BK=16, double-buffered) ----------------
template <bool KM>
__device__ __forceinline__ void ldg_tile(const uint* __restrict__ P, int ld, int k0, int c0,
                                         uint4 (&r)[2], int t) {
#pragma unroll
    for (int i = 0; i < 2; i++) {
        int f = i * 256 + t;
        if (KM) {
            int kk = f >> 5, cc = (f & 31) << 2;
            r[i] = *(const uint4*)(P + (size_t)(k0 + kk) * ld + c0 + cc);
        } else {
            int cc = f >> 2, kk = (f & 3) << 2;
            r[i] = *(const uint4*)(P + (size_t)(c0 + cc) * ld + k0 + kk);
        }
    }
}
template <bool KM>
__device__ __forceinline__ void sts_tile(unsigned short* hi, unsigned short* lo,
                                         const uint4 (&r)[2], int t) {
#pragma unroll
    for (int i = 0; i < 2; i++) {
        int f = i * 256 + t;
        uint w0 = r[i].x, w1 = r[i].y, w2 = r[i].z, w3 = r[i].w;
        if (KM) {
            int kk = f >> 5, cc = (f & 31) << 2;
            hi[(cc + 0) * 24 + kk] = (unsigned short)w0;
            hi[(cc + 1) * 24 + kk] = (unsigned short)w1;
            hi[(cc + 2) * 24 + kk] = (unsigned short)w2;
            hi[(cc + 3) * 24 + kk] = (unsigned short)w3;
            lo[(cc + 0) * 24 + kk] = (unsigned short)(w0 >> 16);
            lo[(cc + 1) * 24 + kk] = (unsigned short)(w1 >> 16);
            lo[(cc + 2) * 24 + kk] = (unsigned short)(w2 >> 16);
            lo[(cc + 3) * 24 + kk] = (unsigned short)(w3 >> 16);
        } else {
            int cc = f >> 2, kk = (f & 3) << 2;
            *(uint*)(hi + cc * 24 + kk)     = prmtb(w0, w1, 0x5410);
            *(uint*)(hi + cc * 24 + kk + 2) = prmtb(w2, w3, 0x5410);
            *(uint*)(lo + cc * 24 + kk)     = prmtb(w0, w1, 0x7632);
            *(uint*)(lo + cc * 24 + kk + 2) = prmtb(w2, w3, 0x7632);
        }
    }
}

template <bool A_KM, bool B_NK>
__global__ __launch_bounds__(256)
void tc_gemm(const uint* __restrict__ A, const uint* __restrict__ B, float* __restrict__ C,
             int K, int lda, int ldb, int ldc,
             long long sA, long long sB, long long sC,
             const float* __restrict__ bias, int biasMode, int outMode) {
    __shared__ unsigned short AsH[2][128 * 24];
    __shared__ unsigned short AsL[2][128 * 24];
    __shared__ unsigned short BsH[2][128 * 24];
    __shared__ unsigned short BsL[2][128 * 24];
    int bz = blockIdx.z;
    A += sA * bz; B += sB * bz;
    float* Cb = C + sC * bz;
    int bm = blockIdx.y * 128, bn = blockIdx.x * 128;
    int t = threadIdx.x, w = t >> 5, lane = t & 31;
    int wm = (w >> 1) * 32, wn = (w & 1) * 64;
    int g = lane >> 2, tg = lane & 3;

    float acc[2][8][4];
#pragma unroll
    for (int mi = 0; mi < 2; mi++)
#pragma unroll
        for (int ni = 0; ni < 8; ni++)
#pragma unroll
            for (int r = 0; r < 4; r++) acc[mi][ni][r] = 0.f;

    uint4 rA[2], rB[2];
    ldg_tile<A_KM>(A, lda, 0, bm, rA, t);
    ldg_tile<!B_NK>(B, ldb, 0, bn, rB, t);
    sts_tile<A_KM>(AsH[0], AsL[0], rA, t);
    sts_tile<!B_NK>(BsH[0], BsL[0], rB, t);
    __syncthreads();

    int T = K / 16, p = 0;
    for (int kt = 0; kt < T; kt++) {
        if (kt + 1 < T) {
            ldg_tile<A_KM>(A, lda, (kt + 1) * 16, bm, rA, t);
            ldg_tile<!B_NK>(B, ldb, (kt + 1) * 16, bn, rB, t);
        }
        uint aH[2][4], aL[2][4], bH[8][2], bL[8][2];
#pragma unroll
        for (int mi = 0; mi < 2; mi++) {
            const unsigned short* pH = AsH[p] + (wm + mi * 16 + g) * 24 + 2 * tg;
            const unsigned short* pL = AsL[p] + (wm + mi * 16 + g) * 24 + 2 * tg;
            aH[mi][0] = *(const uint*)(pH);      aH[mi][1] = *(const uint*)(pH + 8 * 24);
            aH[mi][2] = *(const uint*)(pH + 8);  aH[mi][3] = *(const uint*)(pH + 8 * 24 + 8);
            aL[mi][0] = *(const uint*)(pL);      aL[mi][1] = *(const uint*)(pL + 8 * 24);
            aL[mi][2] = *(const uint*)(pL + 8);  aL[mi][3] = *(const uint*)(pL + 8 * 24 + 8);
        }
#pragma unroll
        for (int ni = 0; ni < 8; ni++) {
            const unsigned short* pH = BsH[p] + (wn + ni * 8 + g) * 24 + 2 * tg;
            const unsigned short* pL = BsL[p] + (wn + ni * 8 + g) * 24 + 2 * tg;
            bH[ni][0] = *(const uint*)(pH); bH[ni][1] = *(const uint*)(pH + 8);
            bL[ni][0] = *(const uint*)(pL); bL[ni][1] = *(const uint*)(pL + 8);
        }
#pragma unroll
        for (int mi = 0; mi < 2; mi++)
#pragma unroll
            for (int ni = 0; ni < 8; ni++) {
                mma_bf(acc[mi][ni], aH[mi], bH[ni]);
                mma_bf(acc[mi][ni], aH[mi], bL[ni]);
                mma_bf(acc[mi][ni], aL[mi], bH[ni]);
            }
        if (kt + 1 < T) {
            p ^= 1;
            sts_tile<A_KM>(AsH[p], AsL[p], rA, t);
            sts_tile<!B_NK>(BsH[p], BsL[p], rB, t);
            __syncthreads();
        }
    }

#pragma unroll
    for (int mi = 0; mi < 2; mi++) {
#pragma unroll
        for (int ni = 0; ni < 8; ni++) {
#pragma unroll
            for (int hf = 0; hf < 2; hf++) {
                int m = bm + wm + mi * 16 + g + hf * 8;
                int n = bn + wn + ni * 8 + 2 * tg;
                float v0 = acc[mi][ni][hf * 2 + 0];
                float v1 = acc[mi][ni][hf * 2 + 1];
                if (biasMode == 1) { float b = bias[m]; v0 += b; v1 += b; }
                if (outMode == 0) {
                    *(float2*)(Cb + (size_t)m * ldc + n) = make_float2(v0, v1);
                } else {
                    uint2 ov = make_uint2(packsplit(v0), packsplit(v1));
                    *(uint2*)((uint*)Cb + (size_t)m * ldc + n) = ov;
                }
            }
        }
    }
}

// ---------------- plain fp16 GEMM: D[M,N] = A[M,K] · B[N,K]^T ----------------
__device__ __forceinline__ void ldst16(const __half* __restrict__ G, size_t ld, int row0, int k0,
                                       __half* __restrict__ Sm, int t) {
    int row = t >> 1, q = (t & 1) * 8;
    uint4 v = *(const uint4*)(G + (size_t)(row0 + row) * ld + k0 + q);
    *(uint4*)(Sm + row * 24 + q) = v;
}

__global__ __launch_bounds__(256)
void hgemm(const __half* __restrict__ A, const __half* __restrict__ B, float* __restrict__ C,
           int K, size_t lda, size_t ldb, int ldc,
           long long sA, long long sB, long long sC,
           const float* __restrict__ bias, int biasMode,
           const float* __restrict__ scaleM, long long sSM,
           const float* __restrict__ addSrc, long long sAdd,
           int actMode, int outMode) {
    __shared__ __half As[2][128 * 24];
    __shared__ __half Bs[2][128 * 24];
    int bz = blockIdx.z;
    A += sA * bz; B += sB * bz;
    float*  CbF = C + sC * bz;
    __half* CbH = (__half*)C + sC * bz;
    int bm = blockIdx.y * 128, bn = blockIdx.x * 128;
    int t = threadIdx.x, w = t >> 5, lane = t & 31;
    int wm = (w >> 1) * 32, wn = (w & 1) * 64;
    int g = lane >> 2, tg = lane & 3;

    float acc[2][8][4];
#pragma unroll
    for (int mi = 0; mi < 2; mi++)
#pragma unroll
        for (int ni = 0; ni < 8; ni++)
#pragma unroll
            for (int r = 0; r < 4; r++) acc[mi][ni][r] = 0.f;

    ldst16(A, lda, bm, 0, As[0], t);
    ldst16(B, ldb, bn, 0, Bs[0], t);
    __syncthreads();

    int T = K / 16, p = 0;
    for (int kt = 0; kt < T; kt++) {
        uint a[2][4], b[8][2];
#pragma unroll
        for (int mi = 0; mi < 2; mi++) {
            const __half* pA = As[p] + (wm + mi * 16 + g) * 24 + 2 * tg;
            a[mi][0] = *(const uint*)(pA);      a[mi][1] = *(const uint*)(pA + 8 * 24);
            a[mi][2] = *(const uint*)(pA + 8);  a[mi][3] = *(const uint*)(pA + 8 * 24 + 8);
        }
#pragma unroll
        for (int ni = 0; ni < 8; ni++) {
            const __half* pB = Bs[p] + (wn + ni * 8 + g) * 24 + 2 * tg;
            b[ni][0] = *(const uint*)(pB); b[ni][1] = *(const uint*)(pB + 8);
        }
#pragma unroll
        for (int mi = 0; mi < 2; mi++)
#pragma unroll
            for (int ni = 0; ni < 8; ni++)
                mma_hf(acc[mi][ni], a[mi], b[ni]);
        if (kt + 1 < T) {
            int q = p ^ 1;
            ldst16(A, lda, bm, (kt + 1) * 16, As[q], t);
            ldst16(B, ldb, bn, (kt + 1) * 16, Bs[q], t);
            p = q;
            __syncthreads();
        }
    }

#pragma unroll
    for (int mi = 0; mi < 2; mi++) {
#pragma unroll
        for (int ni = 0; ni < 8; ni++) {
#pragma unroll
            for (int hf = 0; hf < 2; hf++) {
                int m = bm + wm + mi * 16 + g + hf * 8;
                int n = bn + wn + ni * 8 + 2 * tg;
                float v0 = acc[mi][ni][hf * 2 + 0];
                float v1 = acc[mi][ni][hf * 2 + 1];
                if (scaleM) { float s = scaleM[sSM * bz + m]; v0 *= s; v1 *= s; }
                if (biasMode == 1) { float b_ = bias[m]; v0 += b_; v1 += b_; }
                if (biasMode == 2) { v0 += bias[n]; v1 += bias[n + 1]; }
                if (actMode == 1) {
                    v0 = (v0 > 0.f) ? v0 : 0.2f * v0;
                    v1 = (v1 > 0.f) ? v1 : 0.2f * v1;
                }
                if (addSrc) {
                    v0 += addSrc[sAdd * bz + (size_t)m * ldc + n];
                    v1 += addSrc[sAdd * bz + (size_t)m * ldc + n + 1];
                }
                if (outMode == 0) {
                    *(float2*)(CbF + (size_t)m * ldc + n) = make_float2(v0, v1);
                } else {
                    *(__half2*)(CbH + (size_t)m * ldc + n) = __floats2half2_rn(v0, v1);
                }
            }
        }
    }
}

// ---------------- host launcher ----------------
extern "C" void kernel_launch(void* const* d_in, const int* in_sizes, int n_in,
                              void* d_out, int out_size) {
    const float* content = (const float*)d_in[0];
    const float* style   = (const float*)d_in[1];
    const float* Wf   = (const float*)d_in[2];
    const float* bf   = (const float*)d_in[3];
    const float* Wg   = (const float*)d_in[4];
    const float* bg   = (const float*)d_in[5];
    const float* Wh   = (const float*)d_in[6];
    const float* bh   = (const float*)d_in[7];
    const float* Wout = (const float*)d_in[8];
    const float* bout = (const float*)d_in[9];
    const float* W1   = (const float*)d_in[10];
    const float* b1   = (const float*)d_in[11];
    const float* W2   = (const float*)d_in[12];
    const float* b2   = (const float*)d_in[13];
    float* out = (float*)d_out;

    uint *mvnC, *mvnS, *Fq, *Gk, *Wfs, *Wgs;
    __half *styleT, *contentT, *styleR, *Hv, *Ot, *T1t, *Whs, *Wos, *W1h;
    float *S, *hmid, *rnC, *rnS, *clampv;
    cudaGetSymbolAddress((void**)&mvnC, g_mvn_c);
    cudaGetSymbolAddress((void**)&mvnS, g_mvn_s);
    cudaGetSymbolAddress((void**)&Fq, g_Fq);
    cudaGetSymbolAddress((void**)&Gk, g_Gk);
    cudaGetSymbolAddress((void**)&S, g_S);
    cudaGetSymbolAddress((void**)&styleT, g_styleT);
    cudaGetSymbolAddress((void**)&contentT, g_contentT);
    cudaGetSymbolAddress((void**)&styleR, g_styleR);
    cudaGetSymbolAddress((void**)&Hv, g_Hv);
    cudaGetSymbolAddress((void**)&Ot, g_Ot);
    cudaGetSymbolAddress((void**)&T1t, g_T1t);
    cudaGetSymbolAddress((void**)&hmid, g_hmid);
    cudaGetSymbolAddress((void**)&rnC, g_rnC);
    cudaGetSymbolAddress((void**)&rnS, g_rnS);
    cudaGetSymbolAddress((void**)&clampv, g_clamp);
    cudaGetSymbolAddress((void**)&Wfs, g_Wfs);
    cudaGetSymbolAddress((void**)&Wgs, g_Wgs);
    cudaGetSymbolAddress((void**)&Whs, g_Whs);
    cudaGetSymbolAddress((void**)&Wos, g_Wos);
    cudaGetSymbolAddress((void**)&W1h, g_W1h);

    const long long CS  = (long long)CDIM * HWD;   // [C,HW] per-batch
    const long long CT  = (long long)HWD * CDIM;   // [HW,C] per-batch
    const long long SS  = (long long)HWD * HWD;
    const long long HSC = (long long)HIDD * CDIM;  // T1t per-batch
    const long long HM  = (long long)HWD * HIDD;   // hmid per-batch

    // 0) weights
    split_kernel<<<CDIM * CDIM / 1024, 256>>>((const float4*)Wf, (uint4*)Wfs);
    split_kernel<<<CDIM * CDIM / 1024, 256>>>((const float4*)Wg, (uint4*)Wgs);
    tohalf_kernel<<<CDIM * CDIM / 1024, 256>>>((const float4*)Wh, Whs);
    tohalf_kernel<<<CDIM * CDIM / 1024, 256>>>((const float4*)Wout, Wos);
    tohalf_kernel<<<HIDD * HWD / 1024, 256>>>((const float4*)W1, W1h);

    // 1) per-(b,c) stats + norms + transposes
    mvn_kernel<<<BDIM * CDIM, 256>>>(content, mvnC);
    mvn_kernel<<<BDIM * CDIM, 256>>>(style, mvnS);
    rnorm_kernel<<<dim3(HWD / 256, BDIM), 256>>>(content, rnC);
    rnorm_kernel<<<dim3(HWD / 256, BDIM), 256>>>(style, rnS);
    dim3 gT(HWD / 32, CDIM / 32, BDIM), bT(32, 8);
    thalf_kernel<<<gT, bT>>>(style, styleT);
    thalf_kernel<<<gT, bT>>>(content, contentT);
    scalehalf_kernel<<<dim3(CDIM * HWD / 1024, BDIM), 256>>>(style, rnS, styleR);

    // 2) precision-critical convs (bf16 3-pass split) -> packed [C,HW]
    dim3 gConv(HWD / 128, CDIM / 128, BDIM);
    tc_gemm<false, false><<<gConv, 256>>>(Wfs, mvnC, (float*)Fq, CDIM, CDIM, HWD, HWD,
        0, CS, CS, bf, 1, 1);
    tc_gemm<false, false><<<gConv, 256>>>(Wgs, mvnS, (float*)Gk, CDIM, CDIM, HWD, HWD,
        0, CS, CS, bg, 1, 1);

    // 3) logits S = Fq^T Gk (split) -> fp32
    dim3 gBig(HWD / 128, HWD / 128, BDIM);
    tc_gemm<true, false><<<gBig, 256>>>(Fq, Gk, S, CDIM, HWD, HWD, HWD,
        CS, CS, SS, nullptr, 0, 0);

    // 4) Hv[c,hw] = Wh[c,:]·styleT[hw,:] + bh (fp16 plain)
    dim3 gHv(HWD / 128, CDIM / 128, BDIM);
    hgemm<<<gHv, 256>>>(Whs, styleT, (float*)Hv, CDIM, CDIM, CDIM, HWD,
        0, CT, CS, bh, 1, nullptr, 0, nullptr, 0, 0, 1);

    // 5) fused clamp path:
    // T1t[o,c] = W1[o,:] · styleR[c,:]   (K=HW)
    dim3 gT1(CDIM / 128, HIDD / 128, BDIM);
    hgemm<<<gT1, 256>>>(W1h, styleR, (float*)T1t, HWD, HWD, HWD, CDIM,
        0, CS, HSC, nullptr, 0, nullptr, 0, nullptr, 0, 0, 1);
    // hmid[k,o] = leaky(rnC[k] * (contentT[k,:]·T1t[o,:]) + b1[o])  (K=C)
    dim3 gT2(HIDD / 128, HWD / 128, BDIM);
    hgemm<<<gT2, 256>>>(contentT, T1t, hmid, CDIM, CDIM, CDIM, HIDD,
        CT, HSC, HM, b1, 2, rnC, HWD, nullptr, 0, 1, 0);

    // 6) psi -> clamp ; softmax+gate (S fp32 -> fp16 Sg in place)
    psi_kernel<<<BDIM * HWD / 4, 128>>>(hmid, W2, b2, clampv);
    softgate_kernel<<<BDIM * HWD, 256>>>(S, clampv);

    // 7) Ot[k,c] = Sg[k,:]·Hv[c,:]  (fp16 plain, K=HW)
    dim3 gO(CDIM / 128, HWD / 128, BDIM);
    hgemm<<<gO, 256>>>((const __half*)S, Hv, (float*)Ot, HWD, (size_t)2 * HWD, HWD, CDIM,
        2 * SS, CS, CT, nullptr, 0, nullptr, 0, nullptr, 0, 0, 1);

    // 8) out[c,hw] = Wout[c,:]·Ot[hw,:] + bout[c] + content  (fp16 plain, K=C)
    dim3 gF(HWD / 128, CDIM / 128, BDIM);
    hgemm<<<gF, 256>>>(Wos, Ot, out, CDIM, CDIM, CDIM, HWD,
        0, CT, CS, bout, 1, nullptr, 0, content, CS, 0, 0);
}

// round 9
// speedup vs baseline: 1.5275x; 1.0945x over previous
#include <cuda_runtime.h>
#include <cuda_bf16.h>
#include <cuda_fp16.h>

typedef unsigned int uint;

#define BDIM 4
#define CDIM 512
#define HWD 4096
#define HIDD 256
#define MAXE 16

// ---------------- scratch ----------------
__device__ uint   g_mvn_c[(size_t)BDIM * CDIM * HWD];
__device__ uint   g_mvn_s[(size_t)BDIM * CDIM * HWD];
__device__ uint   g_Fq[(size_t)BDIM * CDIM * HWD];     // [C,HW] packed split
__device__ uint   g_Gk[(size_t)BDIM * CDIM * HWD];
__device__ float  g_S[(size_t)BDIM * HWD * HWD];       // fp32 logits
__device__ __half g_styleT[(size_t)BDIM * HWD * CDIM]; // [HW,C] fp16
__device__ __half g_contentT[(size_t)BDIM * HWD * CDIM];
__device__ __half g_styleR[(size_t)BDIM * CDIM * HWD]; // style*rnS [C,HW] fp16
__device__ __half g_HvT[(size_t)BDIM * HWD * CDIM];    // value feats [HW,C] fp16
__device__ __half g_Ot[(size_t)BDIM * HWD * CDIM];     // [HW,C] fp16
__device__ __half g_T1t[(size_t)BDIM * HIDD * CDIM];   // [HID,C] fp16
__device__ float  g_hmid[(size_t)BDIM * HWD * HIDD];
__device__ float  g_rnC[BDIM * HWD];
__device__ float  g_rnS[BDIM * HWD];
__device__ float  g_clamp[BDIM * HWD];
__device__ int    g_scnt[BDIM * HWD];
__device__ int    g_sidx[(size_t)BDIM * HWD * MAXE];
__device__ float  g_sval[(size_t)BDIM * HWD * MAXE];
__device__ uint   g_Wfs[CDIM * CDIM];
__device__ uint   g_Wgs[CDIM * CDIM];
__device__ __half g_Whs[CDIM * CDIM];
__device__ __half g_Wos[CDIM * CDIM];
__device__ __half g_W1h[HIDD * HWD];

// ---------------- helpers ----------------
__device__ __forceinline__ uint packsplit(float x) {
    __nv_bfloat16 h = __float2bfloat16_rn(x);
    float hf = __bfloat162float(h);
    __nv_bfloat16 l = __float2bfloat16_rn(x - hf);
    return (uint)__bfloat16_as_ushort(h) | ((uint)__bfloat16_as_ushort(l) << 16);
}
__device__ __forceinline__ uint prmtb(uint a, uint b, uint s) {
    uint d;
    asm("prmt.b32 %0,%1,%2,%3;" : "=r"(d) : "r"(a), "r"(b), "r"(s));
    return d;
}
__device__ __forceinline__ void mma_bf(float* d, const uint* a, const uint* b) {
    asm volatile(
        "mma.sync.aligned.m16n8k16.row.col.f32.bf16.bf16.f32 "
        "{%0,%1,%2,%3},{%4,%5,%6,%7},{%8,%9},{%0,%1,%2,%3};"
        : "+f"(d[0]), "+f"(d[1]), "+f"(d[2]), "+f"(d[3])
        : "r"(a[0]), "r"(a[1]), "r"(a[2]), "r"(a[3]), "r"(b[0]), "r"(b[1]));
}
__device__ __forceinline__ void mma_hf(float* d, const uint* a, const uint* b) {
    asm volatile(
        "mma.sync.aligned.m16n8k16.row.col.f32.f16.f16.f32 "
        "{%0,%1,%2,%3},{%4,%5,%6,%7},{%8,%9},{%0,%1,%2,%3};"
        : "+f"(d[0]), "+f"(d[1]), "+f"(d[2]), "+f"(d[3])
        : "r"(a[0]), "r"(a[1]), "r"(a[2]), "r"(a[3]), "r"(b[0]), "r"(b[1]));
}

// ---------------- elementwise kernels ----------------
__global__ void split_kernel(const float4* __restrict__ x, uint4* __restrict__ y) {
    int i = blockIdx.x * 256 + threadIdx.x;
    float4 v = x[i];
    y[i] = make_uint4(packsplit(v.x), packsplit(v.y), packsplit(v.z), packsplit(v.w));
}

__global__ void tohalf_kernel(const float4* __restrict__ x, __half* __restrict__ y) {
    int i = blockIdx.x * 256 + threadIdx.x;
    float4 v = x[i];
    __half2* o = (__half2*)(y + (size_t)i * 4);
    o[0] = __floats2half2_rn(v.x, v.y);
    o[1] = __floats2half2_rn(v.z, v.w);
}

__global__ void scalehalf_kernel(const float* __restrict__ x, const float* __restrict__ rn,
                                 __half* __restrict__ y) {
    int b = blockIdx.y;
    size_t i = (size_t)blockIdx.x * 256 + threadIdx.x;
    size_t base = (size_t)b * CDIM * HWD + i * 4;
    int l = (int)((i * 4) % HWD);
    float4 v = *(const float4*)(x + base);
    float4 r = *(const float4*)(rn + (size_t)b * HWD + l);
    __half2* o = (__half2*)(y + base);
    o[0] = __floats2half2_rn(v.x * r.x, v.y * r.y);
    o[1] = __floats2half2_rn(v.z * r.z, v.w * r.w);
}

__global__ void mvn_kernel(const float* __restrict__ x, uint* __restrict__ y) {
    int bc = blockIdx.x;
    const float* px = x + (size_t)bc * HWD;
    uint* py = y + (size_t)bc * HWD;
    int t = threadIdx.x;
    float s = 0.f, s2 = 0.f;
    for (int i = t; i < HWD; i += 256) { float v = px[i]; s += v; s2 += v * v; }
    __shared__ float r1[256], r2[256];
    r1[t] = s; r2[t] = s2; __syncthreads();
    for (int o = 128; o > 0; o >>= 1) {
        if (t < o) { r1[t] += r1[t + o]; r2[t] += r2[t + o]; }
        __syncthreads();
    }
    float mean = r1[0] * (1.0f / HWD);
    float var = (r2[0] - (float)HWD * mean * mean) * (1.0f / (HWD - 1));
    float inv = rsqrtf(var + 1e-5f);
    for (int i = t; i < HWD; i += 256) py[i] = packsplit((px[i] - mean) * inv);
}

__global__ void rnorm_kernel(const float* __restrict__ x, float* __restrict__ rn) {
    int b = blockIdx.y;
    int k = blockIdx.x * 256 + threadIdx.x;
    const float* px = x + (size_t)b * CDIM * HWD + k;
    float s = 0.f;
#pragma unroll 8
    for (int c = 0; c < CDIM; c++) { float v = px[(size_t)c * HWD]; s += v * v; }
    rn[b * HWD + k] = 1.0f / fmaxf(sqrtf(s), 1e-12f);
}

__global__ void thalf_kernel(const float* __restrict__ x, __half* __restrict__ y) {
    __shared__ float tile[32][33];
    int b = blockIdx.z;
    int c0 = blockIdx.y * 32, h0 = blockIdx.x * 32;
    int tx = threadIdx.x, ty = threadIdx.y;
#pragma unroll
    for (int j = 0; j < 4; j++) {
        int c = c0 + ty + j * 8;
        tile[ty + j * 8][tx] = x[((size_t)b * CDIM + c) * HWD + h0 + tx];
    }
    __syncthreads();
#pragma unroll
    for (int j = 0; j < 4; j++) {
        int h = h0 + ty + j * 8;
        y[((size_t)b * HWD + h) * CDIM + c0 + tx] = __float2half_rn(tile[tx][ty + j * 8]);
    }
}

__global__ void psi_kernel(const float* __restrict__ hmid, const float* __restrict__ W2,
                           const float* __restrict__ b2, float* __restrict__ clampv) {
    int row = blockIdx.x * 4 + (threadIdx.x >> 5);
    int lane = threadIdx.x & 31;
    const float* p = hmid + (size_t)row * HIDD;
    float s = 0.f;
#pragma unroll
    for (int j = lane; j < HIDD; j += 32) s += p[j] * W2[j];
#pragma unroll
    for (int o = 16; o > 0; o >>= 1) s += __shfl_xor_sync(0xffffffffu, s, o);
    if (lane == 0) {
        float psi = 1.f / (1.f + __expf(-(s + b2[0])));
        clampv[row] = psi * 0.5f + 0.4f;
    }
}

// softmax + gate + DETERMINISTIC sparse extraction.
// gate = sigmoid(50(S - cv)); entries with S <= cv - 0.3 have gate <= 3.1e-7 (dropped;
// total dropped mass <= ~1.5e-5). Kept entries need S > cv-0.3 >= 0.1 => count <= 9 < MAXE.
__global__ void softgate_sparse_kernel(const float* __restrict__ S, const float* __restrict__ clampv,
                                       int* __restrict__ scnt, int* __restrict__ sidx,
                                       float* __restrict__ sval) {
    size_t row = blockIdx.x;
    const float* p = S + row * HWD;
    __shared__ float buf[HWD];
    __shared__ float red[256];
    int t = threadIdx.x;
    float mx = -1e30f;
    for (int i = t; i < HWD; i += 256) { float v = p[i]; buf[i] = v; mx = fmaxf(mx, v); }
    red[t] = mx; __syncthreads();
    for (int o = 128; o > 0; o >>= 1) { if (t < o) red[t] = fmaxf(red[t], red[t + o]); __syncthreads(); }
    mx = red[0]; __syncthreads();
    float sum = 0.f;
    for (int i = t; i < HWD; i += 256) { float e = __expf(buf[i] - mx); buf[i] = e; sum += e; }
    red[t] = sum; __syncthreads();
    for (int o = 128; o > 0; o >>= 1) { if (t < o) red[t] += red[t + o]; __syncthreads(); }
    float inv = 1.0f / red[0];
    float cv = clampv[row];
    // warp 0: ordered ballot compaction
    if (t < 32) {
        int cnt = 0;
        for (int i0 = 0; i0 < HWD; i0 += 32) {
            int l = i0 + t;
            float d = buf[l] * inv - cv;
            bool q = d > -0.3f;
            uint m = __ballot_sync(0xffffffffu, q);
            if (q) {
                int pos = cnt + __popc(m & ((1u << t) - 1u));
                if (pos < MAXE) {
                    sidx[row * MAXE + pos] = l;
                    sval[row * MAXE + pos] = 1.0f / (1.0f + __expf(-50.0f * d));
                }
            }
            cnt += __popc(m);
        }
        if (t == 0) scnt[row] = cnt < MAXE ? cnt : MAXE;
    }
}

// Ot[row, c] = sum_j gate_j * HvT[l_j, c]
__global__ void sparseO_kernel(const __half* __restrict__ HvT, const int* __restrict__ scnt,
                               const int* __restrict__ sidx, const float* __restrict__ sval,
                               __half* __restrict__ Ot) {
    int row = blockIdx.x;                   // b*HWD + k
    int b = row >> 12;
    int t = threadIdx.x;                    // 128 threads
    int c = t * 4;
    const __half* base = HvT + (size_t)b * HWD * CDIM + c;
    float a0 = 0.f, a1 = 0.f, a2 = 0.f, a3 = 0.f;
    int cnt = scnt[row];
    for (int j = 0; j < cnt; j++) {
        int l = sidx[row * MAXE + j];
        float g = sval[row * MAXE + j];
        uint2 v = *(const uint2*)(base + (size_t)l * CDIM);
        float2 f0 = __half22float2(*(__half2*)&v.x);
        float2 f1 = __half22float2(*(__half2*)&v.y);
        a0 += g * f0.x; a1 += g * f0.y; a2 += g * f1.x; a3 += g * f1.y;
    }
    uint2 o;
    *(__half2*)&o.x = __floats2half2_rn(a0, a1);
    *(__half2*)&o.y = __floats2half2_rn(a2, a3);
    *(uint2*)(Ot + (size_t)row * CDIM + c) = o;
}

// ---------------- bf16-split GEMM (unchanged, known-good) ----------------
template <bool KM>
__device__ __forceinline__ void ldg_tile(const uint* __restrict__ P, int ld, int k0, int c0,
                                         uint4 (&r)[2], int t) {
#pragma unroll
    for (int i = 0; i < 2; i++) {
        int f = i * 256 + t;
        if (KM) {
            int kk = f >> 5, cc = (f & 31) << 2;
            r[i] = *(const uint4*)(P + (size_t)(k0 + kk) * ld + c0 + cc);
        } else {
            int cc = f >> 2, kk = (f & 3) << 2;
            r[i] = *(const uint4*)(P + (size_t)(c0 + cc) * ld + k0 + kk);
        }
    }
}
template <bool KM>
__device__ __forceinline__ void sts_tile(unsigned short* hi, unsigned short* lo,
                                         const uint4 (&r)[2], int t) {
#pragma unroll
    for (int i = 0; i < 2; i++) {
        int f = i * 256 + t;
        uint w0 = r[i].x, w1 = r[i].y, w2 = r[i].z, w3 = r[i].w;
        if (KM) {
            int kk = f >> 5, cc = (f & 31) << 2;
            hi[(cc + 0) * 24 + kk] = (unsigned short)w0;
            hi[(cc + 1) * 24 + kk] = (unsigned short)w1;
            hi[(cc + 2) * 24 + kk] = (unsigned short)w2;
            hi[(cc + 3) * 24 + kk] = (unsigned short)w3;
            lo[(cc + 0) * 24 + kk] = (unsigned short)(w0 >> 16);
            lo[(cc + 1) * 24 + kk] = (unsigned short)(w1 >> 16);
            lo[(cc + 2) * 24 + kk] = (unsigned short)(w2 >> 16);
            lo[(cc + 3) * 24 + kk] = (unsigned short)(w3 >> 16);
        } else {
            int cc = f >> 2, kk = (f & 3) << 2;
            *(uint*)(hi + cc * 24 + kk)     = prmtb(w0, w1, 0x5410);
            *(uint*)(hi + cc * 24 + kk + 2) = prmtb(w2, w3, 0x5410);
            *(uint*)(lo + cc * 24 + kk)     = prmtb(w0, w1, 0x7632);
            *(uint*)(lo + cc * 24 + kk + 2) = prmtb(w2, w3, 0x7632);
        }
    }
}

template <bool A_KM, bool B_NK>
__global__ __launch_bounds__(256)
void tc_gemm(const uint* __restrict__ A, const uint* __restrict__ B, float* __restrict__ C,
             int K, int lda, int ldb, int ldc,
             long long sA, long long sB, long long sC,
             const float* __restrict__ bias, int biasMode, int outMode) {
    __shared__ unsigned short AsH[2][128 * 24];
    __shared__ unsigned short AsL[2][128 * 24];
    __shared__ unsigned short BsH[2][128 * 24];
    __shared__ unsigned short BsL[2][128 * 24];
    int bz = blockIdx.z;
    A += sA * bz; B += sB * bz;
    float* Cb = C + sC * bz;
    int bm = blockIdx.y * 128, bn = blockIdx.x * 128;
    int t = threadIdx.x, w = t >> 5, lane = t & 31;
    int wm = (w >> 1) * 32, wn = (w & 1) * 64;
    int g = lane >> 2, tg = lane & 3;

    float acc[2][8][4];
#pragma unroll
    for (int mi = 0; mi < 2; mi++)
#pragma unroll
        for (int ni = 0; ni < 8; ni++)
#pragma unroll
            for (int r = 0; r < 4; r++) acc[mi][ni][r] = 0.f;

    uint4 rA[2], rB[2];
    ldg_tile<A_KM>(A, lda, 0, bm, rA, t);
    ldg_tile<!B_NK>(B, ldb, 0, bn, rB, t);
    sts_tile<A_KM>(AsH[0], AsL[0], rA, t);
    sts_tile<!B_NK>(BsH[0], BsL[0], rB, t);
    __syncthreads();

    int T = K / 16, p = 0;
    for (int kt = 0; kt < T; kt++) {
        if (kt + 1 < T) {
            ldg_tile<A_KM>(A, lda, (kt + 1) * 16, bm, rA, t);
            ldg_tile<!B_NK>(B, ldb, (kt + 1) * 16, bn, rB, t);
        }
        uint aH[2][4], aL[2][4], bH[8][2], bL[8][2];
#pragma unroll
        for (int mi = 0; mi < 2; mi++) {
            const unsigned short* pH = AsH[p] + (wm + mi * 16 + g) * 24 + 2 * tg;
            const unsigned short* pL = AsL[p] + (wm + mi * 16 + g) * 24 + 2 * tg;
            aH[mi][0] = *(const uint*)(pH);      aH[mi][1] = *(const uint*)(pH + 8 * 24);
            aH[mi][2] = *(const uint*)(pH + 8);  aH[mi][3] = *(const uint*)(pH + 8 * 24 + 8);
            aL[mi][0] = *(const uint*)(pL);      aL[mi][1] = *(const uint*)(pL + 8 * 24);
            aL[mi][2] = *(const uint*)(pL + 8);  aL[mi][3] = *(const uint*)(pL + 8 * 24 + 8);
        }
#pragma unroll
        for (int ni = 0; ni < 8; ni++) {
            const unsigned short* pH = BsH[p] + (wn + ni * 8 + g) * 24 + 2 * tg;
            const unsigned short* pL = BsL[p] + (wn + ni * 8 + g) * 24 + 2 * tg;
            bH[ni][0] = *(const uint*)(pH); bH[ni][1] = *(const uint*)(pH + 8);
            bL[ni][0] = *(const uint*)(pL); bL[ni][1] = *(const uint*)(pL + 8);
        }
#pragma unroll
        for (int mi = 0; mi < 2; mi++)
#pragma unroll
            for (int ni = 0; ni < 8; ni++) {
                mma_bf(acc[mi][ni], aH[mi], bH[ni]);
                mma_bf(acc[mi][ni], aH[mi], bL[ni]);
                mma_bf(acc[mi][ni], aL[mi], bH[ni]);
            }
        if (kt + 1 < T) {
            p ^= 1;
            sts_tile<A_KM>(AsH[p], AsL[p], rA, t);
            sts_tile<!B_NK>(BsH[p], BsL[p], rB, t);
            __syncthreads();
        }
    }

#pragma unroll
    for (int mi = 0; mi < 2; mi++) {
#pragma unroll
        for (int ni = 0; ni < 8; ni++) {
#pragma unroll
            for (int hf = 0; hf < 2; hf++) {
                int m = bm + wm + mi * 16 + g + hf * 8;
                int n = bn + wn + ni * 8 + 2 * tg;
                float v0 = acc[mi][ni][hf * 2 + 0];
                float v1 = acc[mi][ni][hf * 2 + 1];
                if (biasMode == 1) { float b = bias[m]; v0 += b; v1 += b; }
                if (outMode == 0) {
                    *(float2*)(Cb + (size_t)m * ldc + n) = make_float2(v0, v1);
                } else {
                    uint2 ov = make_uint2(packsplit(v0), packsplit(v1));
                    *(uint2*)((uint*)Cb + (size_t)m * ldc + n) = ov;
                }
            }
        }
    }
}

// ---------------- fp16 GEMM with register prefetch ----------------
__device__ __forceinline__ uint4 ldg16(const __half* __restrict__ G, size_t ld, int row0, int k0, int t) {
    int row = t >> 1, q = (t & 1) * 8;
    return *(const uint4*)(G + (size_t)(row0 + row) * ld + k0 + q);
}
__device__ __forceinline__ void sts16(__half* __restrict__ Sm, uint4 v, int t) {
    int row = t >> 1, q = (t & 1) * 8;
    *(uint4*)(Sm + row * 24 + q) = v;
}

__global__ __launch_bounds__(256)
void hgemm(const __half* __restrict__ A, const __half* __restrict__ B, float* __restrict__ C,
           int K, size_t lda, size_t ldb, int ldc,
           long long sA, long long sB, long long sC,
           const float* __restrict__ bias, int biasMode,
           const float* __restrict__ scaleM, long long sSM,
           const float* __restrict__ addSrc, long long sAdd,
           int actMode, int outMode) {
    __shared__ __half As[2][128 * 24];
    __shared__ __half Bs[2][128 * 24];
    int bz = blockIdx.z;
    A += sA * bz; B += sB * bz;
    float*  CbF = C + sC * bz;
    __half* CbH = (__half*)C + sC * bz;
    int bm = blockIdx.y * 128, bn = blockIdx.x * 128;
    int t = threadIdx.x, w = t >> 5, lane = t & 31;
    int wm = (w >> 1) * 32, wn = (w & 1) * 64;
    int g = lane >> 2, tg = lane & 3;

    float acc[2][8][4];
#pragma unroll
    for (int mi = 0; mi < 2; mi++)
#pragma unroll
        for (int ni = 0; ni < 8; ni++)
#pragma unroll
            for (int r = 0; r < 4; r++) acc[mi][ni][r] = 0.f;

    uint4 rA = ldg16(A, lda, bm, 0, t);
    uint4 rB = ldg16(B, ldb, bn, 0, t);
    sts16(As[0], rA, t);
    sts16(Bs[0], rB, t);
    __syncthreads();

    int T = K / 16, p = 0;
    for (int kt = 0; kt < T; kt++) {
        if (kt + 1 < T) {
            rA = ldg16(A, lda, bm, (kt + 1) * 16, t);
            rB = ldg16(B, ldb, bn, (kt + 1) * 16, t);
        }
        uint a[2][4], b[8][2];
#pragma unroll
        for (int mi = 0; mi < 2; mi++) {
            const __half* pA = As[p] + (wm + mi * 16 + g) * 24 + 2 * tg;
            a[mi][0] = *(const uint*)(pA);      a[mi][1] = *(const uint*)(pA + 8 * 24);
            a[mi][2] = *(const uint*)(pA + 8);  a[mi][3] = *(const uint*)(pA + 8 * 24 + 8);
        }
#pragma unroll
        for (int ni = 0; ni < 8; ni++) {
            const __half* pB = Bs[p] + (wn + ni * 8 + g) * 24 + 2 * tg;
            b[ni][0] = *(const uint*)(pB); b[ni][1] = *(const uint*)(pB + 8);
        }
#pragma unroll
        for (int mi = 0; mi < 2; mi++)
#pragma unroll
            for (int ni = 0; ni < 8; ni++)
                mma_hf(acc[mi][ni], a[mi], b[ni]);
        if (kt + 1 < T) {
            p ^= 1;
            sts16(As[p], rA, t);
            sts16(Bs[p], rB, t);
            __syncthreads();
        }
    }

#pragma unroll
    for (int mi = 0; mi < 2; mi++) {
#pragma unroll
        for (int ni = 0; ni < 8; ni++) {
#pragma unroll
            for (int hf = 0; hf < 2; hf++) {
                int m = bm + wm + mi * 16 + g + hf * 8;
                int n = bn + wn + ni * 8 + 2 * tg;
                float v0 = acc[mi][ni][hf * 2 + 0];
                float v1 = acc[mi][ni][hf * 2 + 1];
                if (scaleM) { float s = scaleM[sSM * bz + m]; v0 *= s; v1 *= s; }
                if (biasMode == 1) { float b_ = bias[m]; v0 += b_; v1 += b_; }
                if (biasMode == 2) { v0 += bias[n]; v1 += bias[n + 1]; }
                if (actMode == 1) {
                    v0 = (v0 > 0.f) ? v0 : 0.2f * v0;
                    v1 = (v1 > 0.f) ? v1 : 0.2f * v1;
                }
                if (addSrc) {
                    v0 += addSrc[sAdd * bz + (size_t)m * ldc + n];
                    v1 += addSrc[sAdd * bz + (size_t)m * ldc + n + 1];
                }
                if (outMode == 0) {
                    *(float2*)(CbF + (size_t)m * ldc + n) = make_float2(v0, v1);
                } else {
                    *(__half2*)(CbH + (size_t)m * ldc + n) = __floats2half2_rn(v0, v1);
                }
            }
        }
    }
}

// ---------------- host launcher ----------------
extern "C" void kernel_launch(void* const* d_in, const int* in_sizes, int n_in,
                              void* d_out, int out_size) {
    const float* content = (const float*)d_in[0];
    const float* style   = (const float*)d_in[1];
    const float* Wf   = (const float*)d_in[2];
    const float* bf   = (const float*)d_in[3];
    const float* Wg   = (const float*)d_in[4];
    const float* bg   = (const float*)d_in[5];
    const float* Wh   = (const float*)d_in[6];
    const float* bh   = (const float*)d_in[7];
    const float* Wout = (const float*)d_in[8];
    const float* bout = (const float*)d_in[9];
    const float* W1   = (const float*)d_in[10];
    const float* b1   = (const float*)d_in[11];
    const float* W2   = (const float*)d_in[12];
    const float* b2   = (const float*)d_in[13];
    float* out = (float*)d_out;

    uint *mvnC, *mvnS, *Fq, *Gk, *Wfs, *Wgs;
    __half *styleT, *contentT, *styleR, *HvT, *Ot, *T1t, *Whs, *Wos, *W1h;
    float *S, *hmid, *rnC, *rnS, *clampv, *sval;
    int *scnt, *sidx;
    cudaGetSymbolAddress((void**)&mvnC, g_mvn_c);
    cudaGetSymbolAddress((void**)&mvnS, g_mvn_s);
    cudaGetSymbolAddress((void**)&Fq, g_Fq);
    cudaGetSymbolAddress((void**)&Gk, g_Gk);
    cudaGetSymbolAddress((void**)&S, g_S);
    cudaGetSymbolAddress((void**)&styleT, g_styleT);
    cudaGetSymbolAddress((void**)&contentT, g_contentT);
    cudaGetSymbolAddress((void**)&styleR, g_styleR);
    cudaGetSymbolAddress((void**)&HvT, g_HvT);
    cudaGetSymbolAddress((void**)&Ot, g_Ot);
    cudaGetSymbolAddress((void**)&T1t, g_T1t);
    cudaGetSymbolAddress((void**)&hmid, g_hmid);
    cudaGetSymbolAddress((void**)&rnC, g_rnC);
    cudaGetSymbolAddress((void**)&rnS, g_rnS);
    cudaGetSymbolAddress((void**)&clampv, g_clamp);
    cudaGetSymbolAddress((void**)&scnt, g_scnt);
    cudaGetSymbolAddress((void**)&sidx, g_sidx);
    cudaGetSymbolAddress((void**)&sval, g_sval);
    cudaGetSymbolAddress((void**)&Wfs, g_Wfs);
    cudaGetSymbolAddress((void**)&Wgs, g_Wgs);
    cudaGetSymbolAddress((void**)&Whs, g_Whs);
    cudaGetSymbolAddress((void**)&Wos, g_Wos);
    cudaGetSymbolAddress((void**)&W1h, g_W1h);

    const long long CS  = (long long)CDIM * HWD;
    const long long CT  = (long long)HWD * CDIM;
    const long long SS  = (long long)HWD * HWD;
    const long long HSC = (long long)HIDD * CDIM;
    const long long HM  = (long long)HWD * HIDD;

    // 0) weights
    split_kernel<<<CDIM * CDIM / 1024, 256>>>((const float4*)Wf, (uint4*)Wfs);
    split_kernel<<<CDIM * CDIM / 1024, 256>>>((const float4*)Wg, (uint4*)Wgs);
    tohalf_kernel<<<CDIM * CDIM / 1024, 256>>>((const float4*)Wh, Whs);
    tohalf_kernel<<<CDIM * CDIM / 1024, 256>>>((const float4*)Wout, Wos);
    tohalf_kernel<<<HIDD * HWD / 1024, 256>>>((const float4*)W1, W1h);

    // 1) stats + norms + transposes
    mvn_kernel<<<BDIM * CDIM, 256>>>(content, mvnC);
    mvn_kernel<<<BDIM * CDIM, 256>>>(style, mvnS);
    rnorm_kernel<<<dim3(HWD / 256, BDIM), 256>>>(content, rnC);
    rnorm_kernel<<<dim3(HWD / 256, BDIM), 256>>>(style, rnS);
    dim3 gT(HWD / 32, CDIM / 32, BDIM), bT(32, 8);
    thalf_kernel<<<gT, bT>>>(style, styleT);
    thalf_kernel<<<gT, bT>>>(content, contentT);
    scalehalf_kernel<<<dim3(CDIM * HWD / 1024, BDIM), 256>>>(style, rnS, styleR);

    // 2) precision-critical convs (bf16 3-pass split) -> packed [C,HW]
    dim3 gConv(HWD / 128, CDIM / 128, BDIM);
    tc_gemm<false, false><<<gConv, 256>>>(Wfs, mvnC, (float*)Fq, CDIM, CDIM, HWD, HWD,
        0, CS, CS, bf, 1, 1);
    tc_gemm<false, false><<<gConv, 256>>>(Wgs, mvnS, (float*)Gk, CDIM, CDIM, HWD, HWD,
        0, CS, CS, bg, 1, 1);

    // 3) logits S = Fq^T Gk (split) -> fp32
    dim3 gBig(HWD / 128, HWD / 128, BDIM);
    tc_gemm<true, false><<<gBig, 256>>>(Fq, Gk, S, CDIM, HWD, HWD, HWD,
        CS, CS, SS, nullptr, 0, 0);

    // 4) HvT[hw,c] = styleT[hw,:]·Wh[c,:] + bh[c]  (fp16 plain)
    dim3 gHv(CDIM / 128, HWD / 128, BDIM);
    hgemm<<<gHv, 256>>>(styleT, Whs, (float*)HvT, CDIM, CDIM, CDIM, CDIM,
        CT, 0, CT, bh, 2, nullptr, 0, nullptr, 0, 0, 1);

    // 5) fused clamp path
    dim3 gT1(CDIM / 128, HIDD / 128, BDIM);
    hgemm<<<gT1, 256>>>(W1h, styleR, (float*)T1t, HWD, HWD, HWD, CDIM,
        0, CS, HSC, nullptr, 0, nullptr, 0, nullptr, 0, 0, 1);
    dim3 gT2(HIDD / 128, HWD / 128, BDIM);
    hgemm<<<gT2, 256>>>(contentT, T1t, hmid, CDIM, CDIM, CDIM, HIDD,
        CT, HSC, HM, b1, 2, rnC, HWD, nullptr, 0, 1, 0);

    // 6) psi -> clamp ; softmax + gate + sparse extraction
    psi_kernel<<<BDIM * HWD / 4, 128>>>(hmid, W2, b2, clampv);
    softgate_sparse_kernel<<<BDIM * HWD, 256>>>(S, clampv, scnt, sidx, sval);

    // 7) sparse O: Ot[k,c] = sum_j gate_j * HvT[l_j, c]
    sparseO_kernel<<<BDIM * HWD, 128>>>(HvT, scnt, sidx, sval, Ot);

    // 8) out[c,hw] = Wout[c,:]·Ot[hw,:] + bout[c] + content  (fp16 plain)
    dim3 gF(HWD / 128, CDIM / 128, BDIM);
    hgemm<<<gF, 256>>>(Wos, Ot, out, CDIM, CDIM, CDIM, HWD,
        0, CT, CS, bout, 1, nullptr, 0, content, CS, 0, 0);
}